// round 1
// baseline (speedup 1.0000x reference)
#include <cuda_runtime.h>
#include <cuda_bf16.h>
#include <cstdint>

// Problem constants
#define BB    2
#define SS    2048
#define DM    1024
#define NH    16
#define NKV   4
#define DH    64
#define ROWS  (BB*SS)          // 4096
#define WINDOW 256
#define NGLOB  4

// ---------------------------------------------------------------------------
// Scratch (device globals; no allocation allowed)
// ---------------------------------------------------------------------------
__device__ float g_qlin[ROWS * (NH*DH)];    // 4096 x 1024  (Q after proj, then norm+rope in place)
__device__ float g_klin[ROWS * (NKV*DH)];   // 4096 x 256
__device__ float g_vlin[ROWS * (NKV*DH)];   // 4096 x 256
__device__ float g_ctx [ROWS * (NH*DH)];    // 4096 x 1024  (attention output, pre-Wo)

// ---------------------------------------------------------------------------
// SGEMM: C[M,N] = A[M,K] @ B[K,N], row-major, all dims multiples of tile.
// 128x128 block tile, BK=8, 256 threads, 8x8 per-thread microtile.
// ---------------------------------------------------------------------------
__global__ void __launch_bounds__(256) sgemm_kernel(
    const float* __restrict__ A, const float* __restrict__ B, float* __restrict__ C,
    int K, int lda, int ldb, int ldc)
{
    __shared__ float As[8][132];   // padded: avoids store conflicts, keeps 16B align (132*4=528)
    __shared__ float Bs[8][128];

    const int tid = threadIdx.x;
    const int tx  = tid & 15;
    const int ty  = tid >> 4;
    const int m0  = blockIdx.x * 128;
    const int n0  = blockIdx.y * 128;

    float acc[8][8];
    #pragma unroll
    for (int i = 0; i < 8; i++)
        #pragma unroll
        for (int j = 0; j < 8; j++) acc[i][j] = 0.f;

    const int ar = tid >> 1;           // 0..127
    const int ac = (tid & 1) * 4;      // 0 or 4
    const float* Aptr = A + (size_t)(m0 + ar) * lda + ac;
    const int br = tid >> 5;           // 0..7
    const int bc = (tid & 31) * 4;     // 0..124
    const float* Bptr = B + (size_t)br * ldb + n0 + bc;

    for (int k0 = 0; k0 < K; k0 += 8) {
        float4 av = *(const float4*)(Aptr + k0);
        As[ac+0][ar] = av.x; As[ac+1][ar] = av.y;
        As[ac+2][ar] = av.z; As[ac+3][ar] = av.w;
        *(float4*)&Bs[br][bc] = *(const float4*)(Bptr + (size_t)k0 * ldb);
        __syncthreads();

        #pragma unroll
        for (int kk = 0; kk < 8; kk++) {
            float a[8], b[8];
            *(float4*)(a)   = *(const float4*)&As[kk][ty*4];
            *(float4*)(a+4) = *(const float4*)&As[kk][64 + ty*4];
            *(float4*)(b)   = *(const float4*)&Bs[kk][tx*4];
            *(float4*)(b+4) = *(const float4*)&Bs[kk][64 + tx*4];
            #pragma unroll
            for (int i = 0; i < 8; i++)
                #pragma unroll
                for (int j = 0; j < 8; j++)
                    acc[i][j] = fmaf(a[i], b[j], acc[i][j]);
        }
        __syncthreads();
    }

    #pragma unroll
    for (int i = 0; i < 8; i++) {
        int row = m0 + ((i < 4) ? (ty*4 + i) : (64 + ty*4 + i - 4));
        float4 v0 = make_float4(acc[i][0], acc[i][1], acc[i][2], acc[i][3]);
        float4 v1 = make_float4(acc[i][4], acc[i][5], acc[i][6], acc[i][7]);
        *(float4*)(C + (size_t)row*ldc + n0 + tx*4)      = v0;
        *(float4*)(C + (size_t)row*ldc + n0 + 64 + tx*4) = v1;
    }
}

// ---------------------------------------------------------------------------
// L2 normalize + RoPE, in place. One warp per (row, head). Q heads 0..15, K heads 16..19.
// Lane l owns the (l, l+32) RoPE pair directly.
// ---------------------------------------------------------------------------
__global__ void __launch_bounds__(256) normrope_kernel(
    const float* __restrict__ cosp, const float* __restrict__ sinp)
{
    int w    = (blockIdx.x * blockDim.x + threadIdx.x) >> 5;
    int lane = threadIdx.x & 31;
    if (w >= ROWS * (NH + NKV)) return;
    int rg = w / (NH + NKV);
    int hh = w - rg * (NH + NKV);
    int s  = rg & (SS - 1);

    float* base;
    if (hh < NH) base = g_qlin + (size_t)rg * (NH*DH) + hh * DH;
    else         base = g_klin + (size_t)rg * (NKV*DH) + (hh - NH) * DH;

    float v0 = base[lane];
    float v1 = base[lane + 32];
    float ssq = v0*v0 + v1*v1;
    #pragma unroll
    for (int o = 16; o > 0; o >>= 1) ssq += __shfl_xor_sync(0xffffffffu, ssq, o);
    float inv = 1.0f / (sqrtf(ssq) + 1e-8f);

    float x1 = v0 * inv, x2 = v1 * inv;
    float c  = cosp[s*32 + lane];
    float sn = sinp[s*32 + lane];
    base[lane]      = x1*c - x2*sn;
    base[lane + 32] = x1*sn + x2*c;
}

// ---------------------------------------------------------------------------
// Flash-style attention with sliding window + global tokens + tanh softcap.
// Block = (q_tile of 64, head, batch). 256 threads: tq=tid>>4 (q-row group),
// tk=tid&15 (key/d group), each thread owns 4x4 microtiles (stride-16 interleave).
// Only tiles {0 (global)} U [kt0..qt] are visited: <=6 per q-tile.
// ---------------------------------------------------------------------------
__global__ void __launch_bounds__(256) attn_kernel()
{
    extern __shared__ float sm[];
    float* Qs = sm;                 // 64 x 65
    float* Ks = sm + 4160;
    float* Vs = sm + 2*4160;
    float* Ps = sm + 3*4160;

    const int qt = blockIdx.x, h = blockIdx.y, b = blockIdx.z;
    const int kh = h >> 2;
    const int tid = threadIdx.x;
    const int tq = tid >> 4;
    const int tk = tid & 15;
    const int qs = qt * 64;

    // Load Q tile (64x64), padded rows of 65
    const float* qbase = g_qlin + (size_t)(b*SS + qs) * (NH*DH) + h * DH;
    #pragma unroll
    for (int i = 0; i < 4; i++) {
        int idx = tid + i*256;
        int r = idx >> 4, c = (idx & 15) * 4;
        float4 v = *(const float4*)(qbase + (size_t)r * (NH*DH) + c);
        Qs[r*65+c] = v.x; Qs[r*65+c+1] = v.y; Qs[r*65+c+2] = v.z; Qs[r*65+c+3] = v.w;
    }

    float m[4], l[4], acc[4][4];
    #pragma unroll
    for (int a = 0; a < 4; a++) {
        m[a] = -1e30f; l[a] = 0.f;
        #pragma unroll
        for (int c = 0; c < 4; c++) acc[a][c] = 0.f;
    }

    const int kt0 = (qs >= WINDOW) ? ((qs - (WINDOW-1)) >> 6) : 0;
    const int nsteps = qt - kt0 + 1 + (kt0 > 0 ? 1 : 0);

    for (int step = 0; step < nsteps; step++) {
        const int kt = (kt0 > 0) ? (step == 0 ? 0 : kt0 + step - 1) : step;

        __syncthreads();   // protect previous iter's Ps/Vs reads
        // Load K, V tiles (64x64 each)
        const float* kb = g_klin + (size_t)(b*SS + kt*64) * (NKV*DH) + kh * DH;
        const float* vb = g_vlin + (size_t)(b*SS + kt*64) * (NKV*DH) + kh * DH;
        #pragma unroll
        for (int i = 0; i < 4; i++) {
            int idx = tid + i*256;
            int r = idx >> 4, c = (idx & 15) * 4;
            float4 kv = *(const float4*)(kb + (size_t)r * (NKV*DH) + c);
            Ks[r*65+c] = kv.x; Ks[r*65+c+1] = kv.y; Ks[r*65+c+2] = kv.z; Ks[r*65+c+3] = kv.w;
            float4 vv = *(const float4*)(vb + (size_t)r * (NKV*DH) + c);
            Vs[r*65+c] = vv.x; Vs[r*65+c+1] = vv.y; Vs[r*65+c+2] = vv.z; Vs[r*65+c+3] = vv.w;
        }
        __syncthreads();

        // Scores: 4x4 per thread, q rows tq+16a, keys tk+16bb
        float sc[4][4];
        #pragma unroll
        for (int a = 0; a < 4; a++)
            #pragma unroll
            for (int bb = 0; bb < 4; bb++) sc[a][bb] = 0.f;

        #pragma unroll 16
        for (int d = 0; d < 64; d++) {
            float qf[4], kf[4];
            #pragma unroll
            for (int a = 0; a < 4; a++)  qf[a]  = Qs[(tq + 16*a)*65 + d];
            #pragma unroll
            for (int bb = 0; bb < 4; bb++) kf[bb] = Ks[(tk + 16*bb)*65 + d];
            #pragma unroll
            for (int a = 0; a < 4; a++)
                #pragma unroll
                for (int bb = 0; bb < 4; bb++)
                    sc[a][bb] = fmaf(qf[a], kf[bb], sc[a][bb]);
        }

        // Softcap + mask + online softmax update
        #pragma unroll
        for (int a = 0; a < 4; a++) {
            const int qabs = qs + tq + 16*a;
            float tmax = -1e30f;
            #pragma unroll
            for (int bb = 0; bb < 4; bb++) {
                const int kabs = kt*64 + tk + 16*bb;
                // s = 15*tanh(dot*0.125/15)
                float x = sc[a][bb] * (0.125f / 15.0f);
                float e = __expf(2.0f * x);
                float val = 15.0f * __fdividef(e - 1.0f, e + 1.0f);
                bool valid = (kabs <= qabs) && ((kabs > qabs - WINDOW) || (kabs < NGLOB));
                sc[a][bb] = valid ? val : -1e30f;
                tmax = fmaxf(tmax, sc[a][bb]);
            }
            #pragma unroll
            for (int o = 8; o > 0; o >>= 1)
                tmax = fmaxf(tmax, __shfl_xor_sync(0xffffffffu, tmax, o, 16));

            float mn = fmaxf(m[a], tmax);
            float scale = __expf(m[a] - mn);
            float psum = 0.f;
            #pragma unroll
            for (int bb = 0; bb < 4; bb++) {
                float p = __expf(sc[a][bb] - mn);
                Ps[(tq + 16*a)*65 + tk + 16*bb] = p;
                psum += p;
            }
            #pragma unroll
            for (int o = 8; o > 0; o >>= 1)
                psum += __shfl_xor_sync(0xffffffffu, psum, o, 16);
            l[a] = l[a] * scale + psum;
            m[a] = mn;
            #pragma unroll
            for (int c = 0; c < 4; c++) acc[a][c] *= scale;
        }
        __syncthreads();

        // Context accumulation: acc[a][c] += sum_k P[q,k] * V[k, d=tk+16c]
        #pragma unroll 8
        for (int k = 0; k < 64; k++) {
            float pv[4], vf[4];
            #pragma unroll
            for (int a = 0; a < 4; a++)  pv[a] = Ps[(tq + 16*a)*65 + k];
            #pragma unroll
            for (int c = 0; c < 4; c++)  vf[c] = Vs[k*65 + tk + 16*c];
            #pragma unroll
            for (int a = 0; a < 4; a++)
                #pragma unroll
                for (int c = 0; c < 4; c++)
                    acc[a][c] = fmaf(pv[a], vf[c], acc[a][c]);
        }
    }

    // Epilogue: normalize and write ctx [b, s, h*64 + d]
    #pragma unroll
    for (int a = 0; a < 4; a++) {
        float inv = 1.0f / l[a];
        float* co = g_ctx + (size_t)(b*SS + qs + tq + 16*a) * (NH*DH) + h * DH;
        #pragma unroll
        for (int c = 0; c < 4; c++)
            co[tk + 16*c] = acc[a][c] * inv;
    }
}

// ---------------------------------------------------------------------------
// Launch
// ---------------------------------------------------------------------------
extern "C" void kernel_launch(void* const* d_in, const int* in_sizes, int n_in,
                              void* d_out, int out_size)
{
    const float* x    = (const float*)d_in[0];
    const float* cosp = (const float*)d_in[1];
    const float* sinp = (const float*)d_in[2];
    // d_in[3] = mask: causal, deterministic -> computed analytically in-kernel
    const float* Wq   = (const float*)d_in[4];
    const float* Wk   = (const float*)d_in[5];
    const float* Wv   = (const float*)d_in[6];
    const float* Wo   = (const float*)d_in[7];
    float* out = (float*)d_out;

    void *p_qlin, *p_klin, *p_vlin, *p_ctx;
    cudaGetSymbolAddress(&p_qlin, g_qlin);
    cudaGetSymbolAddress(&p_klin, g_klin);
    cudaGetSymbolAddress(&p_vlin, g_vlin);
    cudaGetSymbolAddress(&p_ctx,  g_ctx);

    cudaFuncSetAttribute(attn_kernel, cudaFuncAttributeMaxDynamicSharedMemorySize, 4*4160*4);

    // 1) Projections
    sgemm_kernel<<<dim3(ROWS/128, (NH*DH)/128), 256>>>(x, Wq, (float*)p_qlin, DM, DM, NH*DH, NH*DH);
    sgemm_kernel<<<dim3(ROWS/128, (NKV*DH)/128), 256>>>(x, Wk, (float*)p_klin, DM, DM, NKV*DH, NKV*DH);
    sgemm_kernel<<<dim3(ROWS/128, (NKV*DH)/128), 256>>>(x, Wv, (float*)p_vlin, DM, DM, NKV*DH, NKV*DH);

    // 2) L2 norm + RoPE in place (Q + K heads only)
    {
        int warps = ROWS * (NH + NKV);
        int blocks = (warps * 32 + 255) / 256;
        normrope_kernel<<<blocks, 256>>>(cosp, sinp);
    }

    // 3) Attention
    attn_kernel<<<dim3(SS/64, NH, BB), 256, 4*4160*4>>>();

    // 4) Output projection
    sgemm_kernel<<<dim3(ROWS/128, DM/128), 256>>>((const float*)p_ctx, Wo, out, NH*DH, NH*DH, DM, DM);
}

// round 4
// speedup vs baseline: 1.5056x; 1.5056x over previous
#include <cuda_runtime.h>
#include <cuda_bf16.h>
#include <cstdint>

// Problem constants
#define BB    2
#define SS    2048
#define DM    1024
#define NH    16
#define NKV   4
#define DH    64
#define ROWS  (BB*SS)          // 4096
#define WINDOW 256
#define NGLOB  4
#define K3    (3*DM)           // 3072 split-K

// ---------------------------------------------------------------------------
// Scratch (device globals; no allocation allowed)
// ---------------------------------------------------------------------------
__device__ float g_qlin[ROWS * (NH*DH)];
__device__ float g_klin[ROWS * (NKV*DH)];
__device__ float g_vlin[ROWS * (NKV*DH)];
__device__ float g_ctx [ROWS * (NH*DH)];
__device__ __nv_bfloat16 g_xsplit  [ROWS * K3];     // x   split [4096, 3072]
__device__ __nv_bfloat16 g_ctxsplit[ROWS * K3];     // ctx split [4096, 3072]
__device__ __nv_bfloat16 g_wqT[(NH*DH)  * K3];      // Wq^T split [1024, 3072]
__device__ __nv_bfloat16 g_wkT[(NKV*DH) * K3];
__device__ __nv_bfloat16 g_wvT[(NKV*DH) * K3];
__device__ __nv_bfloat16 g_woT[DM * K3];

// ---------------------------------------------------------------------------
// Split kernels: fp32 -> 3-term bf16 hi/lo layout
//   A-side: [R, 3C] = [hi | hi | lo]     (row-major, same row ordering as A)
//   B-side: W [K, N] -> [N, 3K] = [hi | lo | hi]  (transposed)
// ---------------------------------------------------------------------------
__global__ void __launch_bounds__(256) split_a_kernel(
    const float* __restrict__ in, __nv_bfloat16* __restrict__ out, int R, int C)
{
    int idx = blockIdx.x * blockDim.x + threadIdx.x;
    if (idx >= R * C) return;
    int r = idx / C, c = idx - r * C;
    float v = in[idx];
    __nv_bfloat16 hi = __float2bfloat16(v);
    __nv_bfloat16 lo = __float2bfloat16(v - __bfloat162float(hi));
    __nv_bfloat16* o = out + (size_t)r * (3 * C);
    o[c] = hi; o[C + c] = hi; o[2 * C + c] = lo;
}

__global__ void __launch_bounds__(256) split_b_kernel(
    const float* __restrict__ W, __nv_bfloat16* __restrict__ out, int K, int N)
{
    int idx = blockIdx.x * blockDim.x + threadIdx.x;
    if (idx >= N * K) return;
    int n = idx / K, k = idx - n * K;
    float v = W[(size_t)k * N + n];
    __nv_bfloat16 hi = __float2bfloat16(v);
    __nv_bfloat16 lo = __float2bfloat16(v - __bfloat162float(hi));
    __nv_bfloat16* o = out + (size_t)n * (3 * K);
    o[k] = hi; o[K + k] = lo; o[2 * K + k] = hi;
}

// ---------------------------------------------------------------------------
// HMMA helpers (base sm_103-legal PTX: mma.sync / ldmatrix / cp.async)
// ---------------------------------------------------------------------------
__device__ __forceinline__ uint32_t smem_u32(const void* p) {
    uint32_t a;
    asm("{ .reg .u64 t; cvta.to.shared.u64 t, %1; cvt.u32.u64 %0, t; }" : "=r"(a) : "l"(p));
    return a;
}
__device__ __forceinline__ void ldsm4(uint32_t* r, uint32_t addr) {
    asm volatile("ldmatrix.sync.aligned.m8n8.x4.shared.b16 {%0,%1,%2,%3}, [%4];"
                 : "=r"(r[0]), "=r"(r[1]), "=r"(r[2]), "=r"(r[3]) : "r"(addr));
}
__device__ __forceinline__ void mma16816(float* d, const uint32_t* a, uint32_t b0, uint32_t b1) {
    asm volatile("mma.sync.aligned.m16n8k16.row.col.f32.bf16.bf16.f32 "
                 "{%0,%1,%2,%3}, {%4,%5,%6,%7}, {%8,%9}, {%0,%1,%2,%3};"
                 : "+f"(d[0]), "+f"(d[1]), "+f"(d[2]), "+f"(d[3])
                 : "r"(a[0]), "r"(a[1]), "r"(a[2]), "r"(a[3]), "r"(b0), "r"(b1));
}
__device__ __forceinline__ void cp16(uint32_t dst, const void* src) {
    asm volatile("cp.async.cg.shared.global [%0], [%1], 16;" :: "r"(dst), "l"(src) : "memory");
}
__device__ __forceinline__ void cp_commit() {
    asm volatile("cp.async.commit_group;" ::: "memory");
}
template <int N>
__device__ __forceinline__ void cp_wait() {
    asm volatile("cp.async.wait_group %0;" :: "n"(N) : "memory");
}

// ---------------------------------------------------------------------------
// HMMA bf16 GEMM: C[M,N] = A[M,Kt] @ B[N,Kt]^T  (both row-major, K-major)
// CTA 128x128, BK=32, 256 threads = 8 warps (2 m x 4 n), warp tile 64x32.
// SMEM rows padded to 80B -> conflict-free ldmatrix. cp.async double buffer.
// ---------------------------------------------------------------------------
#define BK       32
#define ROWB     80                      // bytes per smem row (32 bf16 + 8 pad)
#define TILEB    (128 * ROWB)            // 10240 B per tile

__global__ void __launch_bounds__(256, 2) hmma_gemm_kernel(
    const __nv_bfloat16* __restrict__ A, const __nv_bfloat16* __restrict__ B,
    float* __restrict__ C, int Kt, int ldc)
{
    __shared__ __align__(16) char smA[2][TILEB];
    __shared__ __align__(16) char smB[2][TILEB];

    const int tid = threadIdx.x;
    const int wid = tid >> 5;
    const int lid = tid & 31;
    const int m0 = blockIdx.x * 128;
    const int n0 = blockIdx.y * 128;
    const int wm = (wid & 1) * 64;    // warp m offset in tile
    const int wn = (wid >> 1) * 32;   // warp n offset in tile

    const uint32_t sA0 = smem_u32(smA[0]);
    const uint32_t sB0 = smem_u32(smB[0]);

    float acc[4][4][4];
    #pragma unroll
    for (int i = 0; i < 4; i++)
        #pragma unroll
        for (int j = 0; j < 4; j++)
            #pragma unroll
            for (int q = 0; q < 4; q++) acc[i][j][q] = 0.f;

    // load mapping: 512 16B-chunks per tile, 2 per thread
    const int r0 = tid >> 2;                // rows 0..63 (+64)
    const int c0 = (tid & 3) * 16;          // byte col 0..48

    const int NC = Kt / BK;

    // prefetch chunk 0
    {
        const int k0e = 0;
        #pragma unroll
        for (int i = 0; i < 2; i++) {
            const int r = r0 + i * 64;
            cp16(sA0 + r * ROWB + c0, A + (size_t)(m0 + r) * Kt + k0e + (c0 >> 1));
            cp16(sB0 + r * ROWB + c0, B + (size_t)(n0 + r) * Kt + k0e + (c0 >> 1));
        }
        cp_commit();
    }

    for (int c = 0; c < NC; c++) {
        const int buf = c & 1;
        // prefetch next
        if (c + 1 < NC) {
            const int nb = buf ^ 1;
            const int k0e = (c + 1) * BK;
            const uint32_t dA = sA0 + nb * TILEB;
            const uint32_t dB = sB0 + nb * TILEB;
            #pragma unroll
            for (int i = 0; i < 2; i++) {
                const int r = r0 + i * 64;
                cp16(dA + r * ROWB + c0, A + (size_t)(m0 + r) * Kt + k0e + (c0 >> 1));
                cp16(dB + r * ROWB + c0, B + (size_t)(n0 + r) * Kt + k0e + (c0 >> 1));
            }
            cp_commit();
            cp_wait<1>();
        } else {
            cp_wait<0>();
        }
        __syncthreads();

        const uint32_t aBase = sA0 + buf * TILEB;
        const uint32_t bBase = sB0 + buf * TILEB;
        const int lr = lid & 15;            // row within 16
        const int lh = (lid >> 4) * 16;     // 0 or 16 bytes (k-half select)

        #pragma unroll
        for (int ks = 0; ks < 2; ks++) {
            const int kb = ks * 32;         // byte offset of this k16 step
            uint32_t am[4][4], bm[2][4];
            #pragma unroll
            for (int mf = 0; mf < 4; mf++)
                ldsm4(am[mf], aBase + (wm + mf * 16 + lr) * ROWB + kb + lh);
            #pragma unroll
            for (int nf2 = 0; nf2 < 2; nf2++)
                ldsm4(bm[nf2], bBase + (wn + nf2 * 16 + lr) * ROWB + kb + lh);
            #pragma unroll
            for (int mf = 0; mf < 4; mf++)
                #pragma unroll
                for (int nf = 0; nf < 4; nf++)
                    mma16816(acc[mf][nf], am[mf], bm[nf >> 1][nf & 1], bm[nf >> 1][(nf & 1) + 2]);
        }
        __syncthreads();
    }

    // Epilogue: direct fp32 stores
    const int qr = lid >> 2;       // 0..7
    const int qc = (lid & 3) * 2;  // 0,2,4,6
    #pragma unroll
    for (int mf = 0; mf < 4; mf++) {
        #pragma unroll
        for (int nf = 0; nf < 4; nf++) {
            float* p0 = C + (size_t)(m0 + wm + mf * 16 + qr) * ldc + n0 + wn + nf * 8 + qc;
            float* p1 = p0 + 8 * ldc;
            p0[0] = acc[mf][nf][0]; p0[1] = acc[mf][nf][1];
            p1[0] = acc[mf][nf][2]; p1[1] = acc[mf][nf][3];
        }
    }
}

// ---------------------------------------------------------------------------
// L2 normalize + RoPE, in place. One warp per (row, head).
// ---------------------------------------------------------------------------
__global__ void __launch_bounds__(256) normrope_kernel(
    const float* __restrict__ cosp, const float* __restrict__ sinp)
{
    int w    = (blockIdx.x * blockDim.x + threadIdx.x) >> 5;
    int lane = threadIdx.x & 31;
    if (w >= ROWS * (NH + NKV)) return;
    int rg = w / (NH + NKV);
    int hh = w - rg * (NH + NKV);
    int s  = rg & (SS - 1);

    float* base;
    if (hh < NH) base = g_qlin + (size_t)rg * (NH*DH) + hh * DH;
    else         base = g_klin + (size_t)rg * (NKV*DH) + (hh - NH) * DH;

    float v0 = base[lane];
    float v1 = base[lane + 32];
    float ssq = v0*v0 + v1*v1;
    #pragma unroll
    for (int o = 16; o > 0; o >>= 1) ssq += __shfl_xor_sync(0xffffffffu, ssq, o);
    float inv = 1.0f / (sqrtf(ssq) + 1e-8f);

    float x1 = v0 * inv, x2 = v1 * inv;
    float c  = cosp[s*32 + lane];
    float sn = sinp[s*32 + lane];
    base[lane]      = x1*c - x2*sn;
    base[lane + 32] = x1*sn + x2*c;
}

// ---------------------------------------------------------------------------
// Flash-style attention with sliding window + global tokens + tanh softcap.
// ---------------------------------------------------------------------------
__global__ void __launch_bounds__(256) attn_kernel()
{
    extern __shared__ float smf[];
    float* Qs = smf;                 // 64 x 65
    float* Ks = smf + 4160;
    float* Vs = smf + 2*4160;
    float* Ps = smf + 3*4160;

    const int qt = blockIdx.x, h = blockIdx.y, b = blockIdx.z;
    const int kh = h >> 2;
    const int tid = threadIdx.x;
    const int tq = tid >> 4;
    const int tk = tid & 15;
    const int qs = qt * 64;

    const float* qbase = g_qlin + (size_t)(b*SS + qs) * (NH*DH) + h * DH;
    #pragma unroll
    for (int i = 0; i < 4; i++) {
        int idx = tid + i*256;
        int r = idx >> 4, c = (idx & 15) * 4;
        float4 v = *(const float4*)(qbase + (size_t)r * (NH*DH) + c);
        Qs[r*65+c] = v.x; Qs[r*65+c+1] = v.y; Qs[r*65+c+2] = v.z; Qs[r*65+c+3] = v.w;
    }

    float m[4], l[4], acc[4][4];
    #pragma unroll
    for (int a = 0; a < 4; a++) {
        m[a] = -1e30f; l[a] = 0.f;
        #pragma unroll
        for (int c = 0; c < 4; c++) acc[a][c] = 0.f;
    }

    const int kt0 = (qs >= WINDOW) ? ((qs - (WINDOW-1)) >> 6) : 0;
    const int nsteps = qt - kt0 + 1 + (kt0 > 0 ? 1 : 0);

    for (int step = 0; step < nsteps; step++) {
        const int kt = (kt0 > 0) ? (step == 0 ? 0 : kt0 + step - 1) : step;

        __syncthreads();
        const float* kb = g_klin + (size_t)(b*SS + kt*64) * (NKV*DH) + kh * DH;
        const float* vb = g_vlin + (size_t)(b*SS + kt*64) * (NKV*DH) + kh * DH;
        #pragma unroll
        for (int i = 0; i < 4; i++) {
            int idx = tid + i*256;
            int r = idx >> 4, c = (idx & 15) * 4;
            float4 kv = *(const float4*)(kb + (size_t)r * (NKV*DH) + c);
            Ks[r*65+c] = kv.x; Ks[r*65+c+1] = kv.y; Ks[r*65+c+2] = kv.z; Ks[r*65+c+3] = kv.w;
            float4 vv = *(const float4*)(vb + (size_t)r * (NKV*DH) + c);
            Vs[r*65+c] = vv.x; Vs[r*65+c+1] = vv.y; Vs[r*65+c+2] = vv.z; Vs[r*65+c+3] = vv.w;
        }
        __syncthreads();

        float sc[4][4];
        #pragma unroll
        for (int a = 0; a < 4; a++)
            #pragma unroll
            for (int bb = 0; bb < 4; bb++) sc[a][bb] = 0.f;

        #pragma unroll 16
        for (int d = 0; d < 64; d++) {
            float qf[4], kf[4];
            #pragma unroll
            for (int a = 0; a < 4; a++)  qf[a]  = Qs[(tq + 16*a)*65 + d];
            #pragma unroll
            for (int bb = 0; bb < 4; bb++) kf[bb] = Ks[(tk + 16*bb)*65 + d];
            #pragma unroll
            for (int a = 0; a < 4; a++)
                #pragma unroll
                for (int bb = 0; bb < 4; bb++)
                    sc[a][bb] = fmaf(qf[a], kf[bb], sc[a][bb]);
        }

        #pragma unroll
        for (int a = 0; a < 4; a++) {
            const int qabs = qs + tq + 16*a;
            float tmax = -1e30f;
            #pragma unroll
            for (int bb = 0; bb < 4; bb++) {
                const int kabs = kt*64 + tk + 16*bb;
                float x = sc[a][bb] * (0.125f / 15.0f);
                float e = __expf(2.0f * x);
                float val = 15.0f * __fdividef(e - 1.0f, e + 1.0f);
                bool valid = (kabs <= qabs) && ((kabs > qabs - WINDOW) || (kabs < NGLOB));
                sc[a][bb] = valid ? val : -1e30f;
                tmax = fmaxf(tmax, sc[a][bb]);
            }
            #pragma unroll
            for (int o = 8; o > 0; o >>= 1)
                tmax = fmaxf(tmax, __shfl_xor_sync(0xffffffffu, tmax, o, 16));

            float mn = fmaxf(m[a], tmax);
            float scale = __expf(m[a] - mn);
            float psum = 0.f;
            #pragma unroll
            for (int bb = 0; bb < 4; bb++) {
                float p = __expf(sc[a][bb] - mn);
                Ps[(tq + 16*a)*65 + tk + 16*bb] = p;
                psum += p;
            }
            #pragma unroll
            for (int o = 8; o > 0; o >>= 1)
                psum += __shfl_xor_sync(0xffffffffu, psum, o, 16);
            l[a] = l[a] * scale + psum;
            m[a] = mn;
            #pragma unroll
            for (int c = 0; c < 4; c++) acc[a][c] *= scale;
        }
        __syncthreads();

        #pragma unroll 8
        for (int k = 0; k < 64; k++) {
            float pv[4], vf[4];
            #pragma unroll
            for (int a = 0; a < 4; a++)  pv[a] = Ps[(tq + 16*a)*65 + k];
            #pragma unroll
            for (int c = 0; c < 4; c++)  vf[c] = Vs[k*65 + tk + 16*c];
            #pragma unroll
            for (int a = 0; a < 4; a++)
                #pragma unroll
                for (int c = 0; c < 4; c++)
                    acc[a][c] = fmaf(pv[a], vf[c], acc[a][c]);
        }
    }

    #pragma unroll
    for (int a = 0; a < 4; a++) {
        float inv = 1.0f / l[a];
        float* co = g_ctx + (size_t)(b*SS + qs + tq + 16*a) * (NH*DH) + h * DH;
        #pragma unroll
        for (int c = 0; c < 4; c++)
            co[tk + 16*c] = acc[a][c] * inv;
    }
}

// ---------------------------------------------------------------------------
// Launch
// ---------------------------------------------------------------------------
extern "C" void kernel_launch(void* const* d_in, const int* in_sizes, int n_in,
                              void* d_out, int out_size)
{
    const float* x    = (const float*)d_in[0];
    const float* cosp = (const float*)d_in[1];
    const float* sinp = (const float*)d_in[2];
    // d_in[3] = mask: deterministic causal -> computed analytically in-kernel
    const float* Wq   = (const float*)d_in[4];
    const float* Wk   = (const float*)d_in[5];
    const float* Wv   = (const float*)d_in[6];
    const float* Wo   = (const float*)d_in[7];
    float* out = (float*)d_out;

    void *p_qlin, *p_klin, *p_vlin, *p_ctx;
    void *p_xs, *p_cs, *p_wqT, *p_wkT, *p_wvT, *p_woT;
    cudaGetSymbolAddress(&p_qlin, g_qlin);
    cudaGetSymbolAddress(&p_klin, g_klin);
    cudaGetSymbolAddress(&p_vlin, g_vlin);
    cudaGetSymbolAddress(&p_ctx,  g_ctx);
    cudaGetSymbolAddress(&p_xs,   g_xsplit);
    cudaGetSymbolAddress(&p_cs,   g_ctxsplit);
    cudaGetSymbolAddress(&p_wqT,  g_wqT);
    cudaGetSymbolAddress(&p_wkT,  g_wkT);
    cudaGetSymbolAddress(&p_wvT,  g_wvT);
    cudaGetSymbolAddress(&p_woT,  g_woT);

    cudaFuncSetAttribute(attn_kernel, cudaFuncAttributeMaxDynamicSharedMemorySize, 4*4160*4);

    // 0) Split conversions
    split_a_kernel<<<(ROWS*DM + 255)/256, 256>>>(x, (__nv_bfloat16*)p_xs, ROWS, DM);
    split_b_kernel<<<(DM*(NH*DH) + 255)/256, 256>>>(Wq, (__nv_bfloat16*)p_wqT, DM, NH*DH);
    split_b_kernel<<<(DM*(NKV*DH) + 255)/256, 256>>>(Wk, (__nv_bfloat16*)p_wkT, DM, NKV*DH);
    split_b_kernel<<<(DM*(NKV*DH) + 255)/256, 256>>>(Wv, (__nv_bfloat16*)p_wvT, DM, NKV*DH);
    split_b_kernel<<<((NH*DH)*DM + 255)/256, 256>>>(Wo, (__nv_bfloat16*)p_woT, NH*DH, DM);

    // 1) Projections (HMMA bf16, 3-term split)
    hmma_gemm_kernel<<<dim3(ROWS/128, (NH*DH)/128), 256>>>(
        (const __nv_bfloat16*)p_xs, (const __nv_bfloat16*)p_wqT, (float*)p_qlin, K3, NH*DH);
    hmma_gemm_kernel<<<dim3(ROWS/128, (NKV*DH)/128), 256>>>(
        (const __nv_bfloat16*)p_xs, (const __nv_bfloat16*)p_wkT, (float*)p_klin, K3, NKV*DH);
    hmma_gemm_kernel<<<dim3(ROWS/128, (NKV*DH)/128), 256>>>(
        (const __nv_bfloat16*)p_xs, (const __nv_bfloat16*)p_wvT, (float*)p_vlin, K3, NKV*DH);

    // 2) L2 norm + RoPE
    {
        int warps = ROWS * (NH + NKV);
        int blocks = (warps * 32 + 255) / 256;
        normrope_kernel<<<blocks, 256>>>(cosp, sinp);
    }

    // 3) Attention
    attn_kernel<<<dim3(SS/64, NH, BB), 256, 4*4160*4>>>();

    // 4) Output projection
    split_a_kernel<<<(ROWS*(NH*DH) + 255)/256, 256>>>((const float*)p_ctx, (__nv_bfloat16*)p_cs, ROWS, NH*DH);
    hmma_gemm_kernel<<<dim3(ROWS/128, DM/128), 256>>>(
        (const __nv_bfloat16*)p_cs, (const __nv_bfloat16*)p_woT, out, K3, DM);
}

// round 5
// speedup vs baseline: 2.0971x; 1.3929x over previous
#include <cuda_runtime.h>
#include <cuda_bf16.h>
#include <cstdint>

// Problem constants
#define BB    2
#define SS    2048
#define DM    1024
#define NH    16
#define NKV   4
#define DH    64
#define ROWS  (BB*SS)          // 4096
#define WINDOW 256
#define NGLOB  4
#define K3    (3*DM)           // 3072 split-K

// ---------------------------------------------------------------------------
// Scratch (device globals; no allocation allowed)
// ---------------------------------------------------------------------------
__device__ float g_qlin[ROWS * (NH*DH)];
__device__ float g_klin[ROWS * (NKV*DH)];
__device__ float g_vlin[ROWS * (NKV*DH)];
__device__ float g_ctx [ROWS * (NH*DH)];
__device__ __nv_bfloat16 g_xsplit  [ROWS * K3];
__device__ __nv_bfloat16 g_ctxsplit[ROWS * K3];
__device__ __nv_bfloat16 g_wqT[(NH*DH)  * K3];
__device__ __nv_bfloat16 g_wkT[(NKV*DH) * K3];
__device__ __nv_bfloat16 g_wvT[(NKV*DH) * K3];
__device__ __nv_bfloat16 g_woT[DM * K3];
// attention operands (bf16)
__device__ __nv_bfloat16 g_qbf[ROWS * (NH*DH)];
__device__ __nv_bfloat16 g_kbf[ROWS * (NKV*DH)];
__device__ __nv_bfloat16 g_vhi[ROWS * (NKV*DH)];
__device__ __nv_bfloat16 g_vlo[ROWS * (NKV*DH)];

// ---------------------------------------------------------------------------
// Split kernels: fp32 -> 3-term bf16 hi/lo layout
// ---------------------------------------------------------------------------
__global__ void __launch_bounds__(256) split_a_kernel(
    const float* __restrict__ in, __nv_bfloat16* __restrict__ out, int R, int C)
{
    int idx = blockIdx.x * blockDim.x + threadIdx.x;
    if (idx >= R * C) return;
    int r = idx / C, c = idx - r * C;
    float v = in[idx];
    __nv_bfloat16 hi = __float2bfloat16(v);
    __nv_bfloat16 lo = __float2bfloat16(v - __bfloat162float(hi));
    __nv_bfloat16* o = out + (size_t)r * (3 * C);
    o[c] = hi; o[C + c] = hi; o[2 * C + c] = lo;
}

__global__ void __launch_bounds__(256) split_b_kernel(
    const float* __restrict__ W, __nv_bfloat16* __restrict__ out, int K, int N)
{
    int idx = blockIdx.x * blockDim.x + threadIdx.x;
    if (idx >= N * K) return;
    int n = idx / K, k = idx - n * K;
    float v = W[(size_t)k * N + n];
    __nv_bfloat16 hi = __float2bfloat16(v);
    __nv_bfloat16 lo = __float2bfloat16(v - __bfloat162float(hi));
    __nv_bfloat16* o = out + (size_t)n * (3 * K);
    o[k] = hi; o[K + k] = lo; o[2 * K + k] = hi;
}

// V -> hi/lo bf16 for attention PV precision
__global__ void __launch_bounds__(256) vsplit_kernel()
{
    int idx = blockIdx.x * blockDim.x + threadIdx.x;
    if (idx >= ROWS * (NKV*DH)) return;
    float v = g_vlin[idx];
    __nv_bfloat16 hi = __float2bfloat16(v);
    g_vhi[idx] = hi;
    g_vlo[idx] = __float2bfloat16(v - __bfloat162float(hi));
}

// ---------------------------------------------------------------------------
// HMMA helpers (base sm_103-legal PTX: mma.sync / ldmatrix / cp.async)
// ---------------------------------------------------------------------------
__device__ __forceinline__ uint32_t smem_u32(const void* p) {
    uint32_t a;
    asm("{ .reg .u64 t; cvta.to.shared.u64 t, %1; cvt.u32.u64 %0, t; }" : "=r"(a) : "l"(p));
    return a;
}
__device__ __forceinline__ void ldsm4(uint32_t* r, uint32_t addr) {
    asm volatile("ldmatrix.sync.aligned.m8n8.x4.shared.b16 {%0,%1,%2,%3}, [%4];"
                 : "=r"(r[0]), "=r"(r[1]), "=r"(r[2]), "=r"(r[3]) : "r"(addr));
}
__device__ __forceinline__ void ldsm4t(uint32_t* r, uint32_t addr) {
    asm volatile("ldmatrix.sync.aligned.m8n8.x4.trans.shared.b16 {%0,%1,%2,%3}, [%4];"
                 : "=r"(r[0]), "=r"(r[1]), "=r"(r[2]), "=r"(r[3]) : "r"(addr));
}
__device__ __forceinline__ void mma16816(float* d, const uint32_t* a, uint32_t b0, uint32_t b1) {
    asm volatile("mma.sync.aligned.m16n8k16.row.col.f32.bf16.bf16.f32 "
                 "{%0,%1,%2,%3}, {%4,%5,%6,%7}, {%8,%9}, {%0,%1,%2,%3};"
                 : "+f"(d[0]), "+f"(d[1]), "+f"(d[2]), "+f"(d[3])
                 : "r"(a[0]), "r"(a[1]), "r"(a[2]), "r"(a[3]), "r"(b0), "r"(b1));
}
__device__ __forceinline__ void cp16(uint32_t dst, const void* src) {
    asm volatile("cp.async.cg.shared.global [%0], [%1], 16;" :: "r"(dst), "l"(src) : "memory");
}
__device__ __forceinline__ void cp_commit() {
    asm volatile("cp.async.commit_group;" ::: "memory");
}
template <int N>
__device__ __forceinline__ void cp_wait() {
    asm volatile("cp.async.wait_group %0;" :: "n"(N) : "memory");
}
__device__ __forceinline__ uint32_t pkbf(float a, float b) {
    __nv_bfloat162 t = __floats2bfloat162_rn(a, b);
    return *(uint32_t*)&t;
}

// ---------------------------------------------------------------------------
// HMMA bf16 GEMM: C[M,N] = A[M,Kt] @ B[N,Kt]^T
// ---------------------------------------------------------------------------
#define BK       32
#define ROWB     80
#define TILEB    (128 * ROWB)

__global__ void __launch_bounds__(256, 2) hmma_gemm_kernel(
    const __nv_bfloat16* __restrict__ A, const __nv_bfloat16* __restrict__ B,
    float* __restrict__ C, int Kt, int ldc)
{
    __shared__ __align__(16) char smA[2][TILEB];
    __shared__ __align__(16) char smB[2][TILEB];

    const int tid = threadIdx.x;
    const int wid = tid >> 5;
    const int lid = tid & 31;
    const int m0 = blockIdx.x * 128;
    const int n0 = blockIdx.y * 128;
    const int wm = (wid & 1) * 64;
    const int wn = (wid >> 1) * 32;

    const uint32_t sA0 = smem_u32(smA[0]);
    const uint32_t sB0 = smem_u32(smB[0]);

    float acc[4][4][4];
    #pragma unroll
    for (int i = 0; i < 4; i++)
        #pragma unroll
        for (int j = 0; j < 4; j++)
            #pragma unroll
            for (int q = 0; q < 4; q++) acc[i][j][q] = 0.f;

    const int r0 = tid >> 2;
    const int c0 = (tid & 3) * 16;
    const int NC = Kt / BK;

    {
        #pragma unroll
        for (int i = 0; i < 2; i++) {
            const int r = r0 + i * 64;
            cp16(sA0 + r * ROWB + c0, A + (size_t)(m0 + r) * Kt + (c0 >> 1));
            cp16(sB0 + r * ROWB + c0, B + (size_t)(n0 + r) * Kt + (c0 >> 1));
        }
        cp_commit();
    }

    for (int c = 0; c < NC; c++) {
        const int buf = c & 1;
        if (c + 1 < NC) {
            const int nb = buf ^ 1;
            const int k0e = (c + 1) * BK;
            const uint32_t dA = sA0 + nb * TILEB;
            const uint32_t dB = sB0 + nb * TILEB;
            #pragma unroll
            for (int i = 0; i < 2; i++) {
                const int r = r0 + i * 64;
                cp16(dA + r * ROWB + c0, A + (size_t)(m0 + r) * Kt + k0e + (c0 >> 1));
                cp16(dB + r * ROWB + c0, B + (size_t)(n0 + r) * Kt + k0e + (c0 >> 1));
            }
            cp_commit();
            cp_wait<1>();
        } else {
            cp_wait<0>();
        }
        __syncthreads();

        const uint32_t aBase = sA0 + buf * TILEB;
        const uint32_t bBase = sB0 + buf * TILEB;
        const int lr = lid & 15;
        const int lh = (lid >> 4) * 16;

        #pragma unroll
        for (int ks = 0; ks < 2; ks++) {
            const int kb = ks * 32;
            uint32_t am[4][4], bm[2][4];
            #pragma unroll
            for (int mf = 0; mf < 4; mf++)
                ldsm4(am[mf], aBase + (wm + mf * 16 + lr) * ROWB + kb + lh);
            #pragma unroll
            for (int nf2 = 0; nf2 < 2; nf2++)
                ldsm4(bm[nf2], bBase + (wn + nf2 * 16 + lr) * ROWB + kb + lh);
            #pragma unroll
            for (int mf = 0; mf < 4; mf++)
                #pragma unroll
                for (int nf = 0; nf < 4; nf++)
                    mma16816(acc[mf][nf], am[mf], bm[nf >> 1][nf & 1], bm[nf >> 1][(nf & 1) + 2]);
        }
        __syncthreads();
    }

    const int qr = lid >> 2;
    const int qc = (lid & 3) * 2;
    #pragma unroll
    for (int mf = 0; mf < 4; mf++) {
        #pragma unroll
        for (int nf = 0; nf < 4; nf++) {
            float* p0 = C + (size_t)(m0 + wm + mf * 16 + qr) * ldc + n0 + wn + nf * 8 + qc;
            float* p1 = p0 + 8 * ldc;
            p0[0] = acc[mf][nf][0]; p0[1] = acc[mf][nf][1];
            p1[0] = acc[mf][nf][2]; p1[1] = acc[mf][nf][3];
        }
    }
}

// ---------------------------------------------------------------------------
// L2 normalize + RoPE; reads fp32 proj, writes bf16 Q/K for HMMA attention.
// ---------------------------------------------------------------------------
__global__ void __launch_bounds__(256) normrope_kernel(
    const float* __restrict__ cosp, const float* __restrict__ sinp)
{
    int w    = (blockIdx.x * blockDim.x + threadIdx.x) >> 5;
    int lane = threadIdx.x & 31;
    if (w >= ROWS * (NH + NKV)) return;
    int rg = w / (NH + NKV);
    int hh = w - rg * (NH + NKV);
    int s  = rg & (SS - 1);

    const float* base;
    __nv_bfloat16* ob;
    if (hh < NH) {
        base = g_qlin + (size_t)rg * (NH*DH) + hh * DH;
        ob   = g_qbf  + (size_t)rg * (NH*DH) + hh * DH;
    } else {
        base = g_klin + (size_t)rg * (NKV*DH) + (hh - NH) * DH;
        ob   = g_kbf  + (size_t)rg * (NKV*DH) + (hh - NH) * DH;
    }

    float v0 = base[lane];
    float v1 = base[lane + 32];
    float ssq = v0*v0 + v1*v1;
    #pragma unroll
    for (int o = 16; o > 0; o >>= 1) ssq += __shfl_xor_sync(0xffffffffu, ssq, o);
    float inv = 1.0f / (sqrtf(ssq) + 1e-8f);

    float x1 = v0 * inv, x2 = v1 * inv;
    float c  = cosp[s*32 + lane];
    float sn = sinp[s*32 + lane];
    ob[lane]      = __float2bfloat16(x1*c - x2*sn);
    ob[lane + 32] = __float2bfloat16(x1*sn + x2*c);
}

// ---------------------------------------------------------------------------
// HMMA flash attention. 64 q-rows per CTA, 4 warps (warp = 16 q-rows).
// QK bf16; softcap == identity (|s|<=0.126); fixed-shift softmax (exp, no max);
// PV via register-resident P hi/lo split x V hi/lo split (3 MMA products).
// smem tiles: 144B row stride -> conflict-free ldmatrix.
// ---------------------------------------------------------------------------
#define ASTR 144

__global__ void __launch_bounds__(128) attn_hmma_kernel()
{
    __shared__ __align__(16) char sQ [64*ASTR];
    __shared__ __align__(16) char sK [64*ASTR];
    __shared__ __align__(16) char sVh[64*ASTR];
    __shared__ __align__(16) char sVl[64*ASTR];

    const int qt = blockIdx.x, h = blockIdx.y, b = blockIdx.z;
    const int kh = h >> 2;
    const int tid = threadIdx.x;
    const int w = tid >> 5, l = tid & 31;
    const int qs = qt * 64;

    const uint32_t uQ = smem_u32(sQ), uK = smem_u32(sK);
    const uint32_t uVh = smem_u32(sVh), uVl = smem_u32(sVl);

    // Q tile: 64 rows x 128B
    {
        const char* qb = (const char*)(g_qbf + (size_t)(b*SS + qs) * (NH*DH) + h * DH);
        #pragma unroll
        for (int i = 0; i < 4; i++) {
            int id = tid + i * 128;
            int r = id >> 3, c = (id & 7) * 16;
            cp16(uQ + r * ASTR + c, qb + (size_t)r * (NH*DH*2) + c);
        }
        cp_commit();
    }

    float acc[8][4];
    #pragma unroll
    for (int j = 0; j < 8; j++)
        #pragma unroll
        for (int e = 0; e < 4; e++) acc[j][e] = 0.f;
    float lsum0 = 0.f, lsum1 = 0.f;

    const int kt0 = (qs >= WINDOW) ? ((qs - (WINDOW-1)) >> 6) : 0;
    const int nsteps = qt - kt0 + 1 + (kt0 > 0 ? 1 : 0);

    for (int step = 0; step < nsteps; step++) {
        const int kt = (kt0 > 0) ? (step == 0 ? 0 : kt0 + step - 1) : step;

        __syncthreads();   // prior compute done before tile overwrite
        {
            const size_t roff = (size_t)(b*SS + kt*64) * (NKV*DH) + kh * DH;
            const char* kb = (const char*)(g_kbf + roff);
            const char* vh = (const char*)(g_vhi + roff);
            const char* vl = (const char*)(g_vlo + roff);
            #pragma unroll
            for (int i = 0; i < 4; i++) {
                int id = tid + i * 128;
                int r = id >> 3, c = (id & 7) * 16;
                cp16(uK  + r * ASTR + c, kb + (size_t)r * (NKV*DH*2) + c);
                cp16(uVh + r * ASTR + c, vh + (size_t)r * (NKV*DH*2) + c);
                cp16(uVl + r * ASTR + c, vl + (size_t)r * (NKV*DH*2) + c);
            }
        }
        cp_commit();
        cp_wait<0>();
        __syncthreads();

        // ---- QK: warp computes 16(q) x 64(key), k = d = 64 ----
        float sc[8][4];
        #pragma unroll
        for (int j = 0; j < 8; j++)
            #pragma unroll
            for (int e = 0; e < 4; e++) sc[j][e] = 0.f;

        #pragma unroll
        for (int kf = 0; kf < 4; kf++) {
            uint32_t am[4];
            ldsm4(am, uQ + ((w << 4) + (l & 15)) * ASTR + kf * 32 + ((l >> 4) << 4));
            #pragma unroll
            for (int ng = 0; ng < 4; ng++) {
                uint32_t bm[4];
                ldsm4(bm, uK + (16*ng + (l & 7) + ((l >> 4) << 3)) * ASTR
                             + kf * 32 + (((l >> 3) & 1) << 4));
                mma16816(sc[2*ng],     am, bm[0], bm[1]);
                mma16816(sc[2*ng + 1], am, bm[2], bm[3]);
            }
        }

        // ---- mask + exp (no softcap: identity; no running max: scores bounded) ----
        const int qa0 = qs + (w << 4) + (l >> 2);
        const int kbb = kt * 64 + 2 * (l & 3);
        #pragma unroll
        for (int j = 0; j < 8; j++) {
            const int kc = kbb + 8 * j;
            #pragma unroll
            for (int e = 0; e < 4; e++) {
                const int q_ = qa0 + ((e >> 1) << 3);
                const int k_ = kc + (e & 1);
                const bool v_ = (k_ <= q_) && ((k_ > q_ - WINDOW) || (k_ < NGLOB));
                float p = v_ ? __expf(0.125f * sc[j][e]) : 0.f;
                sc[j][e] = p;
                if (e < 2) lsum0 += p; else lsum1 += p;
            }
        }

        // ---- PV: P (regs, hi/lo) x V (smem hi/lo), drop lo*lo ----
        #pragma unroll
        for (int kf = 0; kf < 4; kf++) {
            float ph[8], pl[8];
            #pragma unroll
            for (int e = 0; e < 4; e++) {
                float p0 = sc[2*kf][e];
                float h0 = __bfloat162float(__float2bfloat16(p0));
                ph[e] = h0; pl[e] = p0 - h0;
                float p1 = sc[2*kf + 1][e];
                float h1 = __bfloat162float(__float2bfloat16(p1));
                ph[4 + e] = h1; pl[4 + e] = p1 - h1;
            }
            uint32_t ah[4], al[4];
            ah[0] = pkbf(ph[0], ph[1]); ah[1] = pkbf(ph[2], ph[3]);
            ah[2] = pkbf(ph[4], ph[5]); ah[3] = pkbf(ph[6], ph[7]);
            al[0] = pkbf(pl[0], pl[1]); al[1] = pkbf(pl[2], pl[3]);
            al[2] = pkbf(pl[4], pl[5]); al[3] = pkbf(pl[6], pl[7]);

            const uint32_t voff = (16*kf + (l & 7) + (((l >> 3) & 1) << 3)) * ASTR
                                  + ((l >> 4) << 4);
            #pragma unroll
            for (int dg = 0; dg < 4; dg++) {
                uint32_t bh[4], bl[4];
                ldsm4t(bh, uVh + voff + dg * 32);
                ldsm4t(bl, uVl + voff + dg * 32);
                mma16816(acc[2*dg],     ah, bh[0], bh[1]);
                mma16816(acc[2*dg + 1], ah, bh[2], bh[3]);
                mma16816(acc[2*dg],     ah, bl[0], bl[1]);
                mma16816(acc[2*dg + 1], ah, bl[2], bl[3]);
                mma16816(acc[2*dg],     al, bh[0], bh[1]);
                mma16816(acc[2*dg + 1], al, bh[2], bh[3]);
            }
        }
    }

    // ---- epilogue: reduce l over the 4 lanes sharing a row, normalize, store ----
    lsum0 += __shfl_xor_sync(0xffffffffu, lsum0, 1, 4);
    lsum0 += __shfl_xor_sync(0xffffffffu, lsum0, 2, 4);
    lsum1 += __shfl_xor_sync(0xffffffffu, lsum1, 1, 4);
    lsum1 += __shfl_xor_sync(0xffffffffu, lsum1, 2, 4);
    const float i0 = 1.f / lsum0;
    const float i1 = 1.f / lsum1;

    float* cb = g_ctx + (size_t)(b*SS + qs + (w << 4) + (l >> 2)) * (NH*DH)
                + h * DH + 2 * (l & 3);
    #pragma unroll
    for (int j = 0; j < 8; j++) {
        float2 v0 = make_float2(acc[j][0] * i0, acc[j][1] * i0);
        *(float2*)(cb + 8*j) = v0;
        float2 v1 = make_float2(acc[j][2] * i1, acc[j][3] * i1);
        *(float2*)(cb + 8 * (NH*DH) + 8*j) = v1;
    }
}

// ---------------------------------------------------------------------------
// Launch
// ---------------------------------------------------------------------------
extern "C" void kernel_launch(void* const* d_in, const int* in_sizes, int n_in,
                              void* d_out, int out_size)
{
    const float* x    = (const float*)d_in[0];
    const float* cosp = (const float*)d_in[1];
    const float* sinp = (const float*)d_in[2];
    // d_in[3] = mask: deterministic causal -> computed analytically in-kernel
    const float* Wq   = (const float*)d_in[4];
    const float* Wk   = (const float*)d_in[5];
    const float* Wv   = (const float*)d_in[6];
    const float* Wo   = (const float*)d_in[7];
    float* out = (float*)d_out;

    void *p_qlin, *p_klin, *p_vlin, *p_ctx;
    void *p_xs, *p_cs, *p_wqT, *p_wkT, *p_wvT, *p_woT;
    cudaGetSymbolAddress(&p_qlin, g_qlin);
    cudaGetSymbolAddress(&p_klin, g_klin);
    cudaGetSymbolAddress(&p_vlin, g_vlin);
    cudaGetSymbolAddress(&p_ctx,  g_ctx);
    cudaGetSymbolAddress(&p_xs,   g_xsplit);
    cudaGetSymbolAddress(&p_cs,   g_ctxsplit);
    cudaGetSymbolAddress(&p_wqT,  g_wqT);
    cudaGetSymbolAddress(&p_wkT,  g_wkT);
    cudaGetSymbolAddress(&p_wvT,  g_wvT);
    cudaGetSymbolAddress(&p_woT,  g_woT);

    // 0) Split conversions
    split_a_kernel<<<(ROWS*DM + 255)/256, 256>>>(x, (__nv_bfloat16*)p_xs, ROWS, DM);
    split_b_kernel<<<(DM*(NH*DH) + 255)/256, 256>>>(Wq, (__nv_bfloat16*)p_wqT, DM, NH*DH);
    split_b_kernel<<<(DM*(NKV*DH) + 255)/256, 256>>>(Wk, (__nv_bfloat16*)p_wkT, DM, NKV*DH);
    split_b_kernel<<<(DM*(NKV*DH) + 255)/256, 256>>>(Wv, (__nv_bfloat16*)p_wvT, DM, NKV*DH);
    split_b_kernel<<<((NH*DH)*DM + 255)/256, 256>>>(Wo, (__nv_bfloat16*)p_woT, NH*DH, DM);

    // 1) Projections (HMMA bf16, 3-term split)
    hmma_gemm_kernel<<<dim3(ROWS/128, (NH*DH)/128), 256>>>(
        (const __nv_bfloat16*)p_xs, (const __nv_bfloat16*)p_wqT, (float*)p_qlin, K3, NH*DH);
    hmma_gemm_kernel<<<dim3(ROWS/128, (NKV*DH)/128), 256>>>(
        (const __nv_bfloat16*)p_xs, (const __nv_bfloat16*)p_wkT, (float*)p_klin, K3, NKV*DH);
    hmma_gemm_kernel<<<dim3(ROWS/128, (NKV*DH)/128), 256>>>(
        (const __nv_bfloat16*)p_xs, (const __nv_bfloat16*)p_wvT, (float*)p_vlin, K3, NKV*DH);

    // 2) L2 norm + RoPE -> bf16 Q/K ; V -> hi/lo bf16
    {
        int warps = ROWS * (NH + NKV);
        int blocks = (warps * 32 + 255) / 256;
        normrope_kernel<<<blocks, 256>>>(cosp, sinp);
    }
    vsplit_kernel<<<(ROWS*(NKV*DH) + 255)/256, 256>>>();

    // 3) Attention (HMMA)
    attn_hmma_kernel<<<dim3(SS/64, NH, BB), 128>>>();

    // 4) Output projection
    split_a_kernel<<<(ROWS*(NH*DH) + 255)/256, 256>>>((const float*)p_ctx, (__nv_bfloat16*)p_cs, ROWS, NH*DH);
    hmma_gemm_kernel<<<dim3(ROWS/128, DM/128), 256>>>(
        (const __nv_bfloat16*)p_cs, (const __nv_bfloat16*)p_woT, out, K3, DM);
}

// round 6
// speedup vs baseline: 2.2132x; 1.0554x over previous
#include <cuda_runtime.h>
#include <cuda_bf16.h>
#include <cstdint>

// Problem constants
#define BB    2
#define SS    2048
#define DM    1024
#define NH    16
#define NKV   4
#define DH    64
#define ROWS  (BB*SS)          // 4096
#define WINDOW 256
#define NGLOB  4
#define K3    (3*DM)           // 3072 split-K
#define NQKV  1536             // fused QKV output width

// ---------------------------------------------------------------------------
// Scratch (device globals; no allocation allowed)
// ---------------------------------------------------------------------------
__device__ float g_qkvlin[ROWS * NQKV];             // fused QKV projection (fp32)
__device__ __nv_bfloat16 g_xsplit  [ROWS * K3];     // x split [4096, 3072]
__device__ __nv_bfloat16 g_ctxsplit[ROWS * K3];     // ctx split (written by attention)
__device__ __nv_bfloat16 g_wqkvT[NQKV * K3];        // fused [Wq|Wk|Wv]^T split
__device__ __nv_bfloat16 g_woT[DM * K3];
// attention operands (bf16)
__device__ __nv_bfloat16 g_qbf[ROWS * (NH*DH)];
__device__ __nv_bfloat16 g_kbf[ROWS * (NKV*DH)];
__device__ __nv_bfloat16 g_vhi[ROWS * (NKV*DH)];
__device__ __nv_bfloat16 g_vlo[ROWS * (NKV*DH)];

// ---------------------------------------------------------------------------
// Split kernels: fp32 -> 3-term bf16 hi/lo layout
// ---------------------------------------------------------------------------
__global__ void __launch_bounds__(256) split_a_kernel(
    const float* __restrict__ in, __nv_bfloat16* __restrict__ out, int R, int C)
{
    int idx = blockIdx.x * blockDim.x + threadIdx.x;
    if (idx >= R * C) return;
    int r = idx / C, c = idx - r * C;
    float v = in[idx];
    __nv_bfloat16 hi = __float2bfloat16(v);
    __nv_bfloat16 lo = __float2bfloat16(v - __bfloat162float(hi));
    __nv_bfloat16* o = out + (size_t)r * (3 * C);
    o[c] = hi; o[C + c] = hi; o[2 * C + c] = lo;
}

__global__ void __launch_bounds__(256) split_b_kernel(
    const float* __restrict__ W, __nv_bfloat16* __restrict__ out, int K, int N)
{
    int idx = blockIdx.x * blockDim.x + threadIdx.x;
    if (idx >= N * K) return;
    int n = idx / K, k = idx - n * K;
    float v = W[(size_t)k * N + n];
    __nv_bfloat16 hi = __float2bfloat16(v);
    __nv_bfloat16 lo = __float2bfloat16(v - __bfloat162float(hi));
    __nv_bfloat16* o = out + (size_t)n * (3 * K);
    o[k] = hi; o[K + k] = lo; o[2 * K + k] = hi;
}

// V (cols 1280..1535 of fused buffer) -> hi/lo bf16
__global__ void __launch_bounds__(256) vsplit_kernel()
{
    int idx = blockIdx.x * blockDim.x + threadIdx.x;
    if (idx >= ROWS * (NKV*DH)) return;
    int r = idx >> 8, c = idx & 255;
    float v = g_qkvlin[(size_t)r * NQKV + 1280 + c];
    __nv_bfloat16 hi = __float2bfloat16(v);
    g_vhi[idx] = hi;
    g_vlo[idx] = __float2bfloat16(v - __bfloat162float(hi));
}

// ---------------------------------------------------------------------------
// HMMA helpers
// ---------------------------------------------------------------------------
__device__ __forceinline__ uint32_t smem_u32(const void* p) {
    uint32_t a;
    asm("{ .reg .u64 t; cvta.to.shared.u64 t, %1; cvt.u32.u64 %0, t; }" : "=r"(a) : "l"(p));
    return a;
}
__device__ __forceinline__ void ldsm4(uint32_t* r, uint32_t addr) {
    asm volatile("ldmatrix.sync.aligned.m8n8.x4.shared.b16 {%0,%1,%2,%3}, [%4];"
                 : "=r"(r[0]), "=r"(r[1]), "=r"(r[2]), "=r"(r[3]) : "r"(addr));
}
__device__ __forceinline__ void ldsm4t(uint32_t* r, uint32_t addr) {
    asm volatile("ldmatrix.sync.aligned.m8n8.x4.trans.shared.b16 {%0,%1,%2,%3}, [%4];"
                 : "=r"(r[0]), "=r"(r[1]), "=r"(r[2]), "=r"(r[3]) : "r"(addr));
}
__device__ __forceinline__ void mma16816(float* d, const uint32_t* a, uint32_t b0, uint32_t b1) {
    asm volatile("mma.sync.aligned.m16n8k16.row.col.f32.bf16.bf16.f32 "
                 "{%0,%1,%2,%3}, {%4,%5,%6,%7}, {%8,%9}, {%0,%1,%2,%3};"
                 : "+f"(d[0]), "+f"(d[1]), "+f"(d[2]), "+f"(d[3])
                 : "r"(a[0]), "r"(a[1]), "r"(a[2]), "r"(a[3]), "r"(b0), "r"(b1));
}
__device__ __forceinline__ void cp16(uint32_t dst, const void* src) {
    asm volatile("cp.async.cg.shared.global [%0], [%1], 16;" :: "r"(dst), "l"(src) : "memory");
}
__device__ __forceinline__ void cp_commit() {
    asm volatile("cp.async.commit_group;" ::: "memory");
}
template <int N>
__device__ __forceinline__ void cp_wait() {
    asm volatile("cp.async.wait_group %0;" :: "n"(N) : "memory");
}
__device__ __forceinline__ uint32_t pkbf(float a, float b) {
    __nv_bfloat162 t = __floats2bfloat162_rn(a, b);
    return *(uint32_t*)&t;
}

// ---------------------------------------------------------------------------
// HMMA bf16 GEMM v2: C[M,N] = A[M,Kt] @ B[N,Kt]^T
// CTA 128x256, 8 warps (2m x 4n grid of 64x64 warp tiles), BK=32,
// 3-stage cp.async pipeline, one __syncthreads per chunk.
// ---------------------------------------------------------------------------
#define BK     32
#define ROWB   80
#define ATILE  (128 * ROWB)              // 10240
#define BTILE  (256 * ROWB)              // 20480
#define STAGE  (ATILE + BTILE)           // 30720
#define GSMEM  (3 * STAGE)               // 92160

__global__ void __launch_bounds__(256) hmma_gemm2_kernel(
    const __nv_bfloat16* __restrict__ A, const __nv_bfloat16* __restrict__ B,
    float* __restrict__ C, int Kt, int ldc)
{
    extern __shared__ __align__(16) char dsm[];
    const int tid = threadIdx.x;
    const int wid = tid >> 5;
    const int lid = tid & 31;
    const int m0 = blockIdx.x * 128;
    const int n0 = blockIdx.y * 256;
    const int wm = (wid & 1) * 64;
    const int wn = (wid >> 1) * 64;

    uint32_t sA[3], sB[3];
    #pragma unroll
    for (int s = 0; s < 3; s++) {
        sA[s] = smem_u32(dsm + s * STAGE);
        sB[s] = sA[s] + ATILE;
    }

    float acc[4][8][4];
    #pragma unroll
    for (int i = 0; i < 4; i++)
        #pragma unroll
        for (int j = 0; j < 8; j++)
            #pragma unroll
            for (int q = 0; q < 4; q++) acc[i][j][q] = 0.f;

    const int ar = tid >> 2;          // 0..63
    const int ac = (tid & 3) * 16;    // byte col 0..48
    const int NC = Kt / BK;

    // prologue: prefetch chunks 0,1
    #pragma unroll
    for (int c = 0; c < 2; c++) {
        const int k0e = c * BK + (ac >> 1);
        #pragma unroll
        for (int i = 0; i < 2; i++)
            cp16(sA[c] + (ar + i * 64) * ROWB + ac, A + (size_t)(m0 + ar + i * 64) * Kt + k0e);
        #pragma unroll
        for (int i = 0; i < 4; i++)
            cp16(sB[c] + (ar + i * 64) * ROWB + ac, B + (size_t)(n0 + ar + i * 64) * Kt + k0e);
        cp_commit();
    }

    int buf = 0, nbuf = 2;
    for (int c = 0; c < NC; c++) {
        cp_wait<1>();
        __syncthreads();

        // prefetch chunk c+2 into nbuf (its old contents were consumed in chunk c-1)
        if (c + 2 < NC) {
            const int k0e = (c + 2) * BK + (ac >> 1);
            #pragma unroll
            for (int i = 0; i < 2; i++)
                cp16(sA[nbuf] + (ar + i * 64) * ROWB + ac, A + (size_t)(m0 + ar + i * 64) * Kt + k0e);
            #pragma unroll
            for (int i = 0; i < 4; i++)
                cp16(sB[nbuf] + (ar + i * 64) * ROWB + ac, B + (size_t)(n0 + ar + i * 64) * Kt + k0e);
        }
        cp_commit();   // empty group at tail keeps the count consistent

        const int lr = lid & 15;
        const int lh = (lid >> 4) * 16;
        #pragma unroll
        for (int ks = 0; ks < 2; ks++) {
            const int kb = ks * 32;
            uint32_t am[4][4], bm[4][4];
            #pragma unroll
            for (int mf = 0; mf < 4; mf++)
                ldsm4(am[mf], sA[buf] + (wm + mf * 16 + lr) * ROWB + kb + lh);
            #pragma unroll
            for (int ng = 0; ng < 4; ng++)
                ldsm4(bm[ng], sB[buf] + (wn + ng * 16 + lr) * ROWB + kb + lh);
            #pragma unroll
            for (int mf = 0; mf < 4; mf++)
                #pragma unroll
                for (int nf = 0; nf < 8; nf++)
                    mma16816(acc[mf][nf], am[mf], bm[nf >> 1][nf & 1], bm[nf >> 1][(nf & 1) + 2]);
        }
        buf = (buf == 2) ? 0 : buf + 1;
        nbuf = (nbuf == 2) ? 0 : nbuf + 1;
    }

    // epilogue
    const int qr = lid >> 2;
    const int qc = (lid & 3) * 2;
    #pragma unroll
    for (int mf = 0; mf < 4; mf++) {
        #pragma unroll
        for (int nf = 0; nf < 8; nf++) {
            float* p0 = C + (size_t)(m0 + wm + mf * 16 + qr) * ldc + n0 + wn + nf * 8 + qc;
            float* p1 = p0 + 8 * ldc;
            p0[0] = acc[mf][nf][0]; p0[1] = acc[mf][nf][1];
            p1[0] = acc[mf][nf][2]; p1[1] = acc[mf][nf][3];
        }
    }
}

// ---------------------------------------------------------------------------
// L2 normalize + RoPE; reads fused fp32 proj, writes bf16 Q/K.
// ---------------------------------------------------------------------------
__global__ void __launch_bounds__(256) normrope_kernel(
    const float* __restrict__ cosp, const float* __restrict__ sinp)
{
    int w    = (blockIdx.x * blockDim.x + threadIdx.x) >> 5;
    int lane = threadIdx.x & 31;
    if (w >= ROWS * (NH + NKV)) return;
    int rg = w / (NH + NKV);
    int hh = w - rg * (NH + NKV);
    int s  = rg & (SS - 1);

    const float* base;
    __nv_bfloat16* ob;
    if (hh < NH) {
        base = g_qkvlin + (size_t)rg * NQKV + hh * DH;
        ob   = g_qbf    + (size_t)rg * (NH*DH) + hh * DH;
    } else {
        base = g_qkvlin + (size_t)rg * NQKV + 1024 + (hh - NH) * DH;
        ob   = g_kbf    + (size_t)rg * (NKV*DH) + (hh - NH) * DH;
    }

    float v0 = base[lane];
    float v1 = base[lane + 32];
    float ssq = v0*v0 + v1*v1;
    #pragma unroll
    for (int o = 16; o > 0; o >>= 1) ssq += __shfl_xor_sync(0xffffffffu, ssq, o);
    float inv = 1.0f / (sqrtf(ssq) + 1e-8f);

    float x1 = v0 * inv, x2 = v1 * inv;
    float c  = cosp[s*32 + lane];
    float sn = sinp[s*32 + lane];
    ob[lane]      = __float2bfloat16(x1*c - x2*sn);
    ob[lane + 32] = __float2bfloat16(x1*sn + x2*c);
}

// ---------------------------------------------------------------------------
// HMMA flash attention (as round 5) + fused ctx hi/lo split epilogue.
// ---------------------------------------------------------------------------
#define ASTR 144

__global__ void __launch_bounds__(128) attn_hmma_kernel()
{
    __shared__ __align__(16) char sQ [64*ASTR];
    __shared__ __align__(16) char sK [64*ASTR];
    __shared__ __align__(16) char sVh[64*ASTR];
    __shared__ __align__(16) char sVl[64*ASTR];

    const int qt = blockIdx.x, h = blockIdx.y, b = blockIdx.z;
    const int kh = h >> 2;
    const int tid = threadIdx.x;
    const int w = tid >> 5, l = tid & 31;
    const int qs = qt * 64;

    const uint32_t uQ = smem_u32(sQ), uK = smem_u32(sK);
    const uint32_t uVh = smem_u32(sVh), uVl = smem_u32(sVl);

    {
        const char* qb = (const char*)(g_qbf + (size_t)(b*SS + qs) * (NH*DH) + h * DH);
        #pragma unroll
        for (int i = 0; i < 4; i++) {
            int id = tid + i * 128;
            int r = id >> 3, c = (id & 7) * 16;
            cp16(uQ + r * ASTR + c, qb + (size_t)r * (NH*DH*2) + c);
        }
        cp_commit();
    }

    float acc[8][4];
    #pragma unroll
    for (int j = 0; j < 8; j++)
        #pragma unroll
        for (int e = 0; e < 4; e++) acc[j][e] = 0.f;
    float lsum0 = 0.f, lsum1 = 0.f;

    const int kt0 = (qs >= WINDOW) ? ((qs - (WINDOW-1)) >> 6) : 0;
    const int nsteps = qt - kt0 + 1 + (kt0 > 0 ? 1 : 0);

    for (int step = 0; step < nsteps; step++) {
        const int kt = (kt0 > 0) ? (step == 0 ? 0 : kt0 + step - 1) : step;

        __syncthreads();
        {
            const size_t roff = (size_t)(b*SS + kt*64) * (NKV*DH) + kh * DH;
            const char* kb = (const char*)(g_kbf + roff);
            const char* vh = (const char*)(g_vhi + roff);
            const char* vl = (const char*)(g_vlo + roff);
            #pragma unroll
            for (int i = 0; i < 4; i++) {
                int id = tid + i * 128;
                int r = id >> 3, c = (id & 7) * 16;
                cp16(uK  + r * ASTR + c, kb + (size_t)r * (NKV*DH*2) + c);
                cp16(uVh + r * ASTR + c, vh + (size_t)r * (NKV*DH*2) + c);
                cp16(uVl + r * ASTR + c, vl + (size_t)r * (NKV*DH*2) + c);
            }
        }
        cp_commit();
        cp_wait<0>();
        __syncthreads();

        float sc[8][4];
        #pragma unroll
        for (int j = 0; j < 8; j++)
            #pragma unroll
            for (int e = 0; e < 4; e++) sc[j][e] = 0.f;

        #pragma unroll
        for (int kf = 0; kf < 4; kf++) {
            uint32_t am[4];
            ldsm4(am, uQ + ((w << 4) + (l & 15)) * ASTR + kf * 32 + ((l >> 4) << 4));
            #pragma unroll
            for (int ng = 0; ng < 4; ng++) {
                uint32_t bm[4];
                ldsm4(bm, uK + (16*ng + (l & 7) + ((l >> 4) << 3)) * ASTR
                             + kf * 32 + (((l >> 3) & 1) << 4));
                mma16816(sc[2*ng],     am, bm[0], bm[1]);
                mma16816(sc[2*ng + 1], am, bm[2], bm[3]);
            }
        }

        const int qa0 = qs + (w << 4) + (l >> 2);
        const int kbb = kt * 64 + 2 * (l & 3);
        #pragma unroll
        for (int j = 0; j < 8; j++) {
            const int kc = kbb + 8 * j;
            #pragma unroll
            for (int e = 0; e < 4; e++) {
                const int q_ = qa0 + ((e >> 1) << 3);
                const int k_ = kc + (e & 1);
                const bool v_ = (k_ <= q_) && ((k_ > q_ - WINDOW) || (k_ < NGLOB));
                float p = v_ ? __expf(0.125f * sc[j][e]) : 0.f;
                sc[j][e] = p;
                if (e < 2) lsum0 += p; else lsum1 += p;
            }
        }

        #pragma unroll
        for (int kf = 0; kf < 4; kf++) {
            float ph[8], pl[8];
            #pragma unroll
            for (int e = 0; e < 4; e++) {
                float p0 = sc[2*kf][e];
                float h0 = __bfloat162float(__float2bfloat16(p0));
                ph[e] = h0; pl[e] = p0 - h0;
                float p1 = sc[2*kf + 1][e];
                float h1 = __bfloat162float(__float2bfloat16(p1));
                ph[4 + e] = h1; pl[4 + e] = p1 - h1;
            }
            uint32_t ah[4], al[4];
            ah[0] = pkbf(ph[0], ph[1]); ah[1] = pkbf(ph[2], ph[3]);
            ah[2] = pkbf(ph[4], ph[5]); ah[3] = pkbf(ph[6], ph[7]);
            al[0] = pkbf(pl[0], pl[1]); al[1] = pkbf(pl[2], pl[3]);
            al[2] = pkbf(pl[4], pl[5]); al[3] = pkbf(pl[6], pl[7]);

            const uint32_t voff = (16*kf + (l & 7) + (((l >> 3) & 1) << 3)) * ASTR
                                  + ((l >> 4) << 4);
            #pragma unroll
            for (int dg = 0; dg < 4; dg++) {
                uint32_t bh[4], bl[4];
                ldsm4t(bh, uVh + voff + dg * 32);
                ldsm4t(bl, uVl + voff + dg * 32);
                mma16816(acc[2*dg],     ah, bh[0], bh[1]);
                mma16816(acc[2*dg + 1], ah, bh[2], bh[3]);
                mma16816(acc[2*dg],     ah, bl[0], bl[1]);
                mma16816(acc[2*dg + 1], ah, bl[2], bl[3]);
                mma16816(acc[2*dg],     al, bh[0], bh[1]);
                mma16816(acc[2*dg + 1], al, bh[2], bh[3]);
            }
        }
    }

    // epilogue: normalize + write ctx directly as [hi|hi|lo] bf16 split
    lsum0 += __shfl_xor_sync(0xffffffffu, lsum0, 1, 4);
    lsum0 += __shfl_xor_sync(0xffffffffu, lsum0, 2, 4);
    lsum1 += __shfl_xor_sync(0xffffffffu, lsum1, 1, 4);
    lsum1 += __shfl_xor_sync(0xffffffffu, lsum1, 2, 4);
    const float i0 = 1.f / lsum0;
    const float i1 = 1.f / lsum1;

    const size_t row0 = (size_t)(b*SS + qs + (w << 4) + (l >> 2));
    __nv_bfloat16* cb0 = g_ctxsplit + row0 * K3 + h * DH + 2 * (l & 3);
    __nv_bfloat16* cb1 = cb0 + 8 * K3;
    #pragma unroll
    for (int j = 0; j < 8; j++) {
        float a0 = acc[j][0] * i0, a1 = acc[j][1] * i0;
        __nv_bfloat162 h2 = __floats2bfloat162_rn(a0, a1);
        __nv_bfloat162 l2 = __floats2bfloat162_rn(a0 - __bfloat162float(h2.x),
                                                  a1 - __bfloat162float(h2.y));
        *(__nv_bfloat162*)(cb0 + 8*j)            = h2;
        *(__nv_bfloat162*)(cb0 + 1024 + 8*j)     = h2;
        *(__nv_bfloat162*)(cb0 + 2048 + 8*j)     = l2;

        float b0 = acc[j][2] * i1, b1 = acc[j][3] * i1;
        __nv_bfloat162 h3 = __floats2bfloat162_rn(b0, b1);
        __nv_bfloat162 l3 = __floats2bfloat162_rn(b0 - __bfloat162float(h3.x),
                                                  b1 - __bfloat162float(h3.y));
        *(__nv_bfloat162*)(cb1 + 8*j)            = h3;
        *(__nv_bfloat162*)(cb1 + 1024 + 8*j)     = h3;
        *(__nv_bfloat162*)(cb1 + 2048 + 8*j)     = l3;
    }
}

// ---------------------------------------------------------------------------
// Launch
// ---------------------------------------------------------------------------
extern "C" void kernel_launch(void* const* d_in, const int* in_sizes, int n_in,
                              void* d_out, int out_size)
{
    const float* x    = (const float*)d_in[0];
    const float* cosp = (const float*)d_in[1];
    const float* sinp = (const float*)d_in[2];
    // d_in[3] = mask: deterministic causal -> computed analytically in-kernel
    const float* Wq   = (const float*)d_in[4];
    const float* Wk   = (const float*)d_in[5];
    const float* Wv   = (const float*)d_in[6];
    const float* Wo   = (const float*)d_in[7];
    float* out = (float*)d_out;

    void *p_qkv, *p_xs, *p_cs, *p_wqkvT, *p_woT;
    cudaGetSymbolAddress(&p_qkv,   g_qkvlin);
    cudaGetSymbolAddress(&p_xs,    g_xsplit);
    cudaGetSymbolAddress(&p_cs,    g_ctxsplit);
    cudaGetSymbolAddress(&p_wqkvT, g_wqkvT);
    cudaGetSymbolAddress(&p_woT,   g_woT);

    cudaFuncSetAttribute(hmma_gemm2_kernel, cudaFuncAttributeMaxDynamicSharedMemorySize, GSMEM);

    // 0) Split conversions (weights fused into one QKV buffer)
    split_a_kernel<<<(ROWS*DM + 255)/256, 256>>>(x, (__nv_bfloat16*)p_xs, ROWS, DM);
    split_b_kernel<<<(DM*(NH*DH) + 255)/256, 256>>>(Wq, (__nv_bfloat16*)p_wqkvT, DM, NH*DH);
    split_b_kernel<<<(DM*(NKV*DH) + 255)/256, 256>>>(Wk, (__nv_bfloat16*)p_wqkvT + (size_t)1024*K3, DM, NKV*DH);
    split_b_kernel<<<(DM*(NKV*DH) + 255)/256, 256>>>(Wv, (__nv_bfloat16*)p_wqkvT + (size_t)1280*K3, DM, NKV*DH);
    split_b_kernel<<<((NH*DH)*DM + 255)/256, 256>>>(Wo, (__nv_bfloat16*)p_woT, NH*DH, DM);

    // 1) Fused QKV projection
    hmma_gemm2_kernel<<<dim3(ROWS/128, NQKV/256), 256, GSMEM>>>(
        (const __nv_bfloat16*)p_xs, (const __nv_bfloat16*)p_wqkvT, (float*)p_qkv, K3, NQKV);

    // 2) L2 norm + RoPE -> bf16 Q/K ; V -> hi/lo bf16
    {
        int warps = ROWS * (NH + NKV);
        int blocks = (warps * 32 + 255) / 256;
        normrope_kernel<<<blocks, 256>>>(cosp, sinp);
    }
    vsplit_kernel<<<(ROWS*(NKV*DH) + 255)/256, 256>>>();

    // 3) Attention (HMMA, writes split ctx directly)
    attn_hmma_kernel<<<dim3(SS/64, NH, BB), 128>>>();

    // 4) Output projection
    hmma_gemm2_kernel<<<dim3(ROWS/128, DM/256), 256, GSMEM>>>(
        (const __nv_bfloat16*)p_cs, (const __nv_bfloat16*)p_woT, out, K3, DM);
}

// round 8
// speedup vs baseline: 3.8247x; 1.7281x over previous
#include <cuda_runtime.h>
#include <cuda_fp16.h>
#include <cstdint>

// Problem constants
#define BB    2
#define SS    2048
#define DM    1024
#define NH    16
#define NKV   4
#define DH    64
#define ROWS  (BB*SS)          // 4096
#define WINDOW 256
#define NGLOB  4
#define NQKV  1536             // fused QKV output width
#define K2    2048             // Wo split-K (ctx hi|lo)

// ---------------------------------------------------------------------------
// Scratch (device globals; no allocation allowed)
// ---------------------------------------------------------------------------
__device__ float  g_qkvlin[ROWS * NQKV];      // fused QKV projection (fp32)
__device__ __half g_xh    [ROWS * DM];        // x in fp16 (single)
__device__ __half g_ctxh  [ROWS * K2];        // ctx [hi | lo] fp16 (attention epilogue)
__device__ __half g_wqkvT [NQKV * DM];        // [Wq|Wk|Wv]^T fp16
__device__ __half g_woT2  [DM * K2];          // Wo^T duplicated [wh | wh]
// attention operands (fp16)
__device__ __half g_qbf[ROWS * (NH*DH)];
__device__ __half g_kbf[ROWS * (NKV*DH)];
__device__ __half g_vhi[ROWS * (NKV*DH)];
__device__ __half g_vlo[ROWS * (NKV*DH)];

// ---------------------------------------------------------------------------
// Conversion kernels
// ---------------------------------------------------------------------------
__global__ void __launch_bounds__(256) conv_x_kernel(const float* __restrict__ in)
{
    int idx = blockIdx.x * blockDim.x + threadIdx.x;
    if (idx >= ROWS * DM) return;
    g_xh[idx] = __float2half(in[idx]);
}

// W [K=1024, N] -> out rows [N, 1024] fp16 (transpose + convert)
__global__ void __launch_bounds__(256) conv_w_kernel(
    const float* __restrict__ W, __half* __restrict__ out, int N)
{
    int idx = blockIdx.x * blockDim.x + threadIdx.x;
    if (idx >= N * DM) return;
    int n = idx >> 10, k = idx & 1023;
    out[(size_t)n * DM + k] = __float2half(W[(size_t)k * N + n]);
}

// Wo [1024,1024] -> [N=1024, 2048] with both K-halves = Wo^T hi
__global__ void __launch_bounds__(256) conv_wo_kernel(const float* __restrict__ W)
{
    int idx = blockIdx.x * blockDim.x + threadIdx.x;
    if (idx >= DM * DM) return;
    int n = idx >> 10, k = idx & 1023;
    __half h = __float2half(W[(size_t)k * DM + n]);
    g_woT2[(size_t)n * K2 + k]        = h;
    g_woT2[(size_t)n * K2 + 1024 + k] = h;
}

// V (cols 1280..1535 of fused buffer) -> hi/lo fp16
__global__ void __launch_bounds__(256) vsplit_kernel()
{
    int idx = blockIdx.x * blockDim.x + threadIdx.x;
    if (idx >= ROWS * (NKV*DH)) return;
    int r = idx >> 8, c = idx & 255;
    float v = g_qkvlin[(size_t)r * NQKV + 1280 + c];
    __half hi = __float2half(v);
    g_vhi[idx] = hi;
    g_vlo[idx] = __float2half(v - __half2float(hi));
}

// ---------------------------------------------------------------------------
// HMMA helpers (fp16)
// ---------------------------------------------------------------------------
__device__ __forceinline__ uint32_t smem_u32(const void* p) {
    uint32_t a;
    asm("{ .reg .u64 t; cvta.to.shared.u64 t, %1; cvt.u32.u64 %0, t; }" : "=r"(a) : "l"(p));
    return a;
}
__device__ __forceinline__ void ldsm4(uint32_t* r, uint32_t addr) {
    asm volatile("ldmatrix.sync.aligned.m8n8.x4.shared.b16 {%0,%1,%2,%3}, [%4];"
                 : "=r"(r[0]), "=r"(r[1]), "=r"(r[2]), "=r"(r[3]) : "r"(addr));
}
__device__ __forceinline__ void ldsm4t(uint32_t* r, uint32_t addr) {
    asm volatile("ldmatrix.sync.aligned.m8n8.x4.trans.shared.b16 {%0,%1,%2,%3}, [%4];"
                 : "=r"(r[0]), "=r"(r[1]), "=r"(r[2]), "=r"(r[3]) : "r"(addr));
}
__device__ __forceinline__ void mma16816h(float* d, const uint32_t* a, uint32_t b0, uint32_t b1) {
    asm volatile("mma.sync.aligned.m16n8k16.row.col.f32.f16.f16.f32 "
                 "{%0,%1,%2,%3}, {%4,%5,%6,%7}, {%8,%9}, {%0,%1,%2,%3};"
                 : "+f"(d[0]), "+f"(d[1]), "+f"(d[2]), "+f"(d[3])
                 : "r"(a[0]), "r"(a[1]), "r"(a[2]), "r"(a[3]), "r"(b0), "r"(b1));
}
__device__ __forceinline__ void cp16(uint32_t dst, const void* src) {
    asm volatile("cp.async.cg.shared.global [%0], [%1], 16;" :: "r"(dst), "l"(src) : "memory");
}
__device__ __forceinline__ void cp_commit() {
    asm volatile("cp.async.commit_group;" ::: "memory");
}
template <int N>
__device__ __forceinline__ void cp_wait() {
    asm volatile("cp.async.wait_group %0;" :: "n"(N) : "memory");
}
__device__ __forceinline__ uint32_t pkh(float a, float b) {
    __half2 t = __floats2half2_rn(a, b);
    return *(uint32_t*)&t;
}

// ---------------------------------------------------------------------------
// HMMA fp16 GEMM: C[M,N] = A[M,Kt] @ B[N,Kt]^T
// CTA 128x256, 8 warps (2m x 4n of 64x64 warp tiles), BK=32, 3-stage cp.async.
// ---------------------------------------------------------------------------
#define BK     32
#define ROWB   80
#define ATILE  (128 * ROWB)
#define BTILE  (256 * ROWB)
#define STAGE  (ATILE + BTILE)
#define GSMEM  (3 * STAGE)               // 92160

__global__ void __launch_bounds__(256) hmma_gemm2_kernel(
    const __half* __restrict__ A, const __half* __restrict__ B,
    float* __restrict__ C, int Kt, int ldc)
{
    extern __shared__ __align__(16) char dsm[];
    const int tid = threadIdx.x;
    const int wid = tid >> 5;
    const int lid = tid & 31;
    const int m0 = blockIdx.x * 128;
    const int n0 = blockIdx.y * 256;
    const int wm = (wid & 1) * 64;
    const int wn = (wid >> 1) * 64;

    uint32_t sA[3], sB[3];
    #pragma unroll
    for (int s = 0; s < 3; s++) {
        sA[s] = smem_u32(dsm + s * STAGE);
        sB[s] = sA[s] + ATILE;
    }

    float acc[4][8][4];
    #pragma unroll
    for (int i = 0; i < 4; i++)
        #pragma unroll
        for (int j = 0; j < 8; j++)
            #pragma unroll
            for (int q = 0; q < 4; q++) acc[i][j][q] = 0.f;

    const int ar = tid >> 2;
    const int ac = (tid & 3) * 16;
    const int NC = Kt / BK;

    #pragma unroll
    for (int c = 0; c < 2; c++) {
        const int k0e = c * BK + (ac >> 1);
        #pragma unroll
        for (int i = 0; i < 2; i++)
            cp16(sA[c] + (ar + i * 64) * ROWB + ac, A + (size_t)(m0 + ar + i * 64) * Kt + k0e);
        #pragma unroll
        for (int i = 0; i < 4; i++)
            cp16(sB[c] + (ar + i * 64) * ROWB + ac, B + (size_t)(n0 + ar + i * 64) * Kt + k0e);
        cp_commit();
    }

    int buf = 0, nbuf = 2;
    for (int c = 0; c < NC; c++) {
        cp_wait<1>();
        __syncthreads();

        if (c + 2 < NC) {
            const int k0e = (c + 2) * BK + (ac >> 1);
            #pragma unroll
            for (int i = 0; i < 2; i++)
                cp16(sA[nbuf] + (ar + i * 64) * ROWB + ac, A + (size_t)(m0 + ar + i * 64) * Kt + k0e);
            #pragma unroll
            for (int i = 0; i < 4; i++)
                cp16(sB[nbuf] + (ar + i * 64) * ROWB + ac, B + (size_t)(n0 + ar + i * 64) * Kt + k0e);
        }
        cp_commit();

        const int lr = lid & 15;
        const int lh = (lid >> 4) * 16;
        #pragma unroll
        for (int ks = 0; ks < 2; ks++) {
            const int kb = ks * 32;
            uint32_t am[4][4], bm[4][4];
            #pragma unroll
            for (int mf = 0; mf < 4; mf++)
                ldsm4(am[mf], sA[buf] + (wm + mf * 16 + lr) * ROWB + kb + lh);
            #pragma unroll
            for (int ng = 0; ng < 4; ng++)
                ldsm4(bm[ng], sB[buf] + (wn + ng * 16 + lr) * ROWB + kb + lh);
            #pragma unroll
            for (int mf = 0; mf < 4; mf++)
                #pragma unroll
                for (int nf = 0; nf < 8; nf++)
                    mma16816h(acc[mf][nf], am[mf], bm[nf >> 1][nf & 1], bm[nf >> 1][(nf & 1) + 2]);
        }
        buf = (buf == 2) ? 0 : buf + 1;
        nbuf = (nbuf == 2) ? 0 : nbuf + 1;
    }

    const int qr = lid >> 2;
    const int qc = (lid & 3) * 2;
    #pragma unroll
    for (int mf = 0; mf < 4; mf++) {
        #pragma unroll
        for (int nf = 0; nf < 8; nf++) {
            float* p0 = C + (size_t)(m0 + wm + mf * 16 + qr) * ldc + n0 + wn + nf * 8 + qc;
            float* p1 = p0 + 8 * ldc;
            p0[0] = acc[mf][nf][0]; p0[1] = acc[mf][nf][1];
            p1[0] = acc[mf][nf][2]; p1[1] = acc[mf][nf][3];
        }
    }
}

// ---------------------------------------------------------------------------
// L2 normalize + RoPE; reads fused fp32 proj, writes fp16 Q/K.
// ---------------------------------------------------------------------------
__global__ void __launch_bounds__(256) normrope_kernel(
    const float* __restrict__ cosp, const float* __restrict__ sinp)
{
    int w    = (blockIdx.x * blockDim.x + threadIdx.x) >> 5;
    int lane = threadIdx.x & 31;
    if (w >= ROWS * (NH + NKV)) return;
    int rg = w / (NH + NKV);
    int hh = w - rg * (NH + NKV);
    int s  = rg & (SS - 1);

    const float* base;
    __half* ob;
    if (hh < NH) {
        base = g_qkvlin + (size_t)rg * NQKV + hh * DH;
        ob   = g_qbf    + (size_t)rg * (NH*DH) + hh * DH;
    } else {
        base = g_qkvlin + (size_t)rg * NQKV + 1024 + (hh - NH) * DH;
        ob   = g_kbf    + (size_t)rg * (NKV*DH) + (hh - NH) * DH;
    }

    float v0 = base[lane];
    float v1 = base[lane + 32];
    float ssq = v0*v0 + v1*v1;
    #pragma unroll
    for (int o = 16; o > 0; o >>= 1) ssq += __shfl_xor_sync(0xffffffffu, ssq, o);
    float inv = 1.0f / (sqrtf(ssq) + 1e-8f);

    float x1 = v0 * inv, x2 = v1 * inv;
    float c  = cosp[s*32 + lane];
    float sn = sinp[s*32 + lane];
    ob[lane]      = __float2half(x1*c - x2*sn);
    ob[lane + 32] = __float2half(x1*sn + x2*c);
}

// ---------------------------------------------------------------------------
// HMMA flash attention (fp16) + fused ctx [hi|lo] epilogue.
// ---------------------------------------------------------------------------
#define ASTR 144

__global__ void __launch_bounds__(128) attn_hmma_kernel()
{
    __shared__ __align__(16) char sQ [64*ASTR];
    __shared__ __align__(16) char sK [64*ASTR];
    __shared__ __align__(16) char sVh[64*ASTR];
    __shared__ __align__(16) char sVl[64*ASTR];

    const int qt = blockIdx.x, h = blockIdx.y, b = blockIdx.z;
    const int kh = h >> 2;
    const int tid = threadIdx.x;
    const int w = tid >> 5, l = tid & 31;
    const int qs = qt * 64;

    const uint32_t uQ = smem_u32(sQ), uK = smem_u32(sK);
    const uint32_t uVh = smem_u32(sVh), uVl = smem_u32(sVl);

    {
        const char* qb = (const char*)(g_qbf + (size_t)(b*SS + qs) * (NH*DH) + h * DH);
        #pragma unroll
        for (int i = 0; i < 4; i++) {
            int id = tid + i * 128;
            int r = id >> 3, c = (id & 7) * 16;
            cp16(uQ + r * ASTR + c, qb + (size_t)r * (NH*DH*2) + c);
        }
        cp_commit();
    }

    float acc[8][4];
    #pragma unroll
    for (int j = 0; j < 8; j++)
        #pragma unroll
        for (int e = 0; e < 4; e++) acc[j][e] = 0.f;
    float lsum0 = 0.f, lsum1 = 0.f;

    const int kt0 = (qs >= WINDOW) ? ((qs - (WINDOW-1)) >> 6) : 0;
    const int nsteps = qt - kt0 + 1 + (kt0 > 0 ? 1 : 0);

    for (int step = 0; step < nsteps; step++) {
        const int kt = (kt0 > 0) ? (step == 0 ? 0 : kt0 + step - 1) : step;

        __syncthreads();
        {
            const size_t roff = (size_t)(b*SS + kt*64) * (NKV*DH) + kh * DH;
            const char* kb = (const char*)(g_kbf + roff);
            const char* vh = (const char*)(g_vhi + roff);
            const char* vl = (const char*)(g_vlo + roff);
            #pragma unroll
            for (int i = 0; i < 4; i++) {
                int id = tid + i * 128;
                int r = id >> 3, c = (id & 7) * 16;
                cp16(uK  + r * ASTR + c, kb + (size_t)r * (NKV*DH*2) + c);
                cp16(uVh + r * ASTR + c, vh + (size_t)r * (NKV*DH*2) + c);
                cp16(uVl + r * ASTR + c, vl + (size_t)r * (NKV*DH*2) + c);
            }
        }
        cp_commit();
        cp_wait<0>();
        __syncthreads();

        float sc[8][4];
        #pragma unroll
        for (int j = 0; j < 8; j++)
            #pragma unroll
            for (int e = 0; e < 4; e++) sc[j][e] = 0.f;

        #pragma unroll
        for (int kf = 0; kf < 4; kf++) {
            uint32_t am[4];
            ldsm4(am, uQ + ((w << 4) + (l & 15)) * ASTR + kf * 32 + ((l >> 4) << 4));
            #pragma unroll
            for (int ng = 0; ng < 4; ng++) {
                uint32_t bm[4];
                ldsm4(bm, uK + (16*ng + (l & 7) + ((l >> 4) << 3)) * ASTR
                             + kf * 32 + (((l >> 3) & 1) << 4));
                mma16816h(sc[2*ng],     am, bm[0], bm[1]);
                mma16816h(sc[2*ng + 1], am, bm[2], bm[3]);
            }
        }

        const int qa0 = qs + (w << 4) + (l >> 2);
        const int kbb = kt * 64 + 2 * (l & 3);
        #pragma unroll
        for (int j = 0; j < 8; j++) {
            const int kc = kbb + 8 * j;
            #pragma unroll
            for (int e = 0; e < 4; e++) {
                const int q_ = qa0 + ((e >> 1) << 3);
                const int k_ = kc + (e & 1);
                const bool v_ = (k_ <= q_) && ((k_ > q_ - WINDOW) || (k_ < NGLOB));
                float p = v_ ? __expf(0.125f * sc[j][e]) : 0.f;
                sc[j][e] = p;
                if (e < 2) lsum0 += p; else lsum1 += p;
            }
        }

        #pragma unroll
        for (int kf = 0; kf < 4; kf++) {
            float ph[8], pl[8];
            #pragma unroll
            for (int e = 0; e < 4; e++) {
                float p0 = sc[2*kf][e];
                float h0 = __half2float(__float2half(p0));
                ph[e] = h0; pl[e] = p0 - h0;
                float p1 = sc[2*kf + 1][e];
                float h1 = __half2float(__float2half(p1));
                ph[4 + e] = h1; pl[4 + e] = p1 - h1;
            }
            uint32_t ah[4], al[4];
            ah[0] = pkh(ph[0], ph[1]); ah[1] = pkh(ph[2], ph[3]);
            ah[2] = pkh(ph[4], ph[5]); ah[3] = pkh(ph[6], ph[7]);
            al[0] = pkh(pl[0], pl[1]); al[1] = pkh(pl[2], pl[3]);
            al[2] = pkh(pl[4], pl[5]); al[3] = pkh(pl[6], pl[7]);

            const uint32_t voff = (16*kf + (l & 7) + (((l >> 3) & 1) << 3)) * ASTR
                                  + ((l >> 4) << 4);
            #pragma unroll
            for (int dg = 0; dg < 4; dg++) {
                uint32_t bh[4], bl[4];
                ldsm4t(bh, uVh + voff + dg * 32);
                ldsm4t(bl, uVl + voff + dg * 32);
                mma16816h(acc[2*dg],     ah, bh[0], bh[1]);
                mma16816h(acc[2*dg + 1], ah, bh[2], bh[3]);
                mma16816h(acc[2*dg],     ah, bl[0], bl[1]);
                mma16816h(acc[2*dg + 1], ah, bl[2], bl[3]);
                mma16816h(acc[2*dg],     al, bh[0], bh[1]);
                mma16816h(acc[2*dg + 1], al, bh[2], bh[3]);
            }
        }
    }

    // epilogue: normalize + write ctx [hi | lo] fp16
    lsum0 += __shfl_xor_sync(0xffffffffu, lsum0, 1, 4);
    lsum0 += __shfl_xor_sync(0xffffffffu, lsum0, 2, 4);
    lsum1 += __shfl_xor_sync(0xffffffffu, lsum1, 1, 4);
    lsum1 += __shfl_xor_sync(0xffffffffu, lsum1, 2, 4);
    const float i0 = 1.f / lsum0;
    const float i1 = 1.f / lsum1;

    const size_t row0 = (size_t)(b*SS + qs + (w << 4) + (l >> 2));
    __half* cb0 = g_ctxh + row0 * K2 + h * DH + 2 * (l & 3);
    __half* cb1 = cb0 + 8 * K2;
    #pragma unroll
    for (int j = 0; j < 8; j++) {
        float a0 = acc[j][0] * i0, a1 = acc[j][1] * i0;
        __half2 h2 = __floats2half2_rn(a0, a1);
        __half2 l2 = __floats2half2_rn(a0 - __half2float(h2.x),
                                       a1 - __half2float(h2.y));
        *(__half2*)(cb0 + 8*j)        = h2;
        *(__half2*)(cb0 + 1024 + 8*j) = l2;

        float b0 = acc[j][2] * i1, b1 = acc[j][3] * i1;
        __half2 h3 = __floats2half2_rn(b0, b1);
        __half2 l3 = __floats2half2_rn(b0 - __half2float(h3.x),
                                       b1 - __half2float(h3.y));
        *(__half2*)(cb1 + 8*j)        = h3;
        *(__half2*)(cb1 + 1024 + 8*j) = l3;
    }
}

// ---------------------------------------------------------------------------
// Launch
// ---------------------------------------------------------------------------
extern "C" void kernel_launch(void* const* d_in, const int* in_sizes, int n_in,
                              void* d_out, int out_size)
{
    const float* x    = (const float*)d_in[0];
    const float* cosp = (const float*)d_in[1];
    const float* sinp = (const float*)d_in[2];
    // d_in[3] = mask: deterministic causal -> computed analytically in-kernel
    const float* Wq   = (const float*)d_in[4];
    const float* Wk   = (const float*)d_in[5];
    const float* Wv   = (const float*)d_in[6];
    const float* Wo   = (const float*)d_in[7];
    float* out = (float*)d_out;

    void *p_qkv, *p_xh, *p_ch, *p_wqkvT, *p_woT2;
    cudaGetSymbolAddress(&p_qkv,   g_qkvlin);
    cudaGetSymbolAddress(&p_xh,    g_xh);
    cudaGetSymbolAddress(&p_ch,    g_ctxh);
    cudaGetSymbolAddress(&p_wqkvT, g_wqkvT);
    cudaGetSymbolAddress(&p_woT2,  g_woT2);

    cudaFuncSetAttribute(hmma_gemm2_kernel, cudaFuncAttributeMaxDynamicSharedMemorySize, GSMEM);

    // 0) Conversions (fp16 single)
    conv_x_kernel<<<(ROWS*DM + 255)/256, 256>>>(x);
    conv_w_kernel<<<((NH*DH)*DM + 255)/256, 256>>>(Wq, (__half*)p_wqkvT, NH*DH);
    conv_w_kernel<<<((NKV*DH)*DM + 255)/256, 256>>>(Wk, (__half*)p_wqkvT + (size_t)1024*DM, NKV*DH);
    conv_w_kernel<<<((NKV*DH)*DM + 255)/256, 256>>>(Wv, (__half*)p_wqkvT + (size_t)1280*DM, NKV*DH);
    conv_wo_kernel<<<(DM*DM + 255)/256, 256>>>(Wo);

    // 1) Fused QKV projection (fp16 single, K=1024)
    hmma_gemm2_kernel<<<dim3(ROWS/128, NQKV/256), 256, GSMEM>>>(
        (const __half*)p_xh, (const __half*)p_wqkvT, (float*)p_qkv, DM, NQKV);

    // 2) L2 norm + RoPE -> fp16 Q/K ; V -> hi/lo fp16
    {
        int warps = ROWS * (NH + NKV);
        int blocks = (warps * 32 + 255) / 256;
        normrope_kernel<<<blocks, 256>>>(cosp, sinp);
    }
    vsplit_kernel<<<(ROWS*(NKV*DH) + 255)/256, 256>>>();

    // 3) Attention (fp16 HMMA, writes ctx [hi|lo] directly)
    attn_hmma_kernel<<<dim3(SS/64, NH, BB), 128>>>();

    // 4) Output projection: [ch|cl] @ [Wh;Wh], K=2048
    hmma_gemm2_kernel<<<dim3(ROWS/128, DM/256), 256, GSMEM>>>(
        (const __half*)p_ch, (const __half*)p_woT2, out, K2, DM);
}

// round 9
// speedup vs baseline: 5.0317x; 1.3156x over previous
#include <cuda_runtime.h>
#include <cuda_fp16.h>
#include <cstdint>

// Problem constants
#define BB    2
#define SS    2048
#define DM    1024
#define NH    16
#define NKV   4
#define DH    64
#define ROWS  (BB*SS)          // 4096
#define WINDOW 256
#define NGLOB  4
#define NQKV  1536             // fused QKV output width

// ---------------------------------------------------------------------------
// Scratch (device globals; no allocation allowed)
// ---------------------------------------------------------------------------
__device__ float  g_qkvlin[ROWS * NQKV];      // fused QK projection (fp32; V cols unused)
__device__ __half g_xh    [ROWS * DM];        // x in fp16
__device__ __half g_ctxh  [ROWS * DM];        // ctx fp16 (attention epilogue)
__device__ __half g_wqkvT [NQKV * DM];        // [Wq|Wk|Wv]^T fp16
__device__ __half g_woT   [DM * DM];          // Wo^T fp16
// attention operands (fp16)
__device__ __half g_qbf[ROWS * (NH*DH)];
__device__ __half g_kbf[ROWS * (NKV*DH)];
__device__ __half g_vh [ROWS * (NKV*DH)];     // V single fp16 (written by GEMM epilogue)

// ---------------------------------------------------------------------------
// Conversion kernels
// ---------------------------------------------------------------------------
__global__ void __launch_bounds__(256) conv_x_kernel(const float* __restrict__ in)
{
    int idx = blockIdx.x * blockDim.x + threadIdx.x;
    if (idx >= ROWS * DM) return;
    g_xh[idx] = __float2half(in[idx]);
}

// All weights in one kernel: Wq/Wk/Wv -> g_wqkvT [1536,1024], Wo -> g_woT [1024,1024]
__global__ void __launch_bounds__(256) conv_weights_kernel(
    const float* __restrict__ Wq, const float* __restrict__ Wk,
    const float* __restrict__ Wv, const float* __restrict__ Wo)
{
    int idx = blockIdx.x * blockDim.x + threadIdx.x;
    const int QKV_TOT = NQKV * DM;             // 1572864
    if (idx < QKV_TOT) {
        int n = idx >> 10, k = idx & 1023;
        float v;
        if (n < 1024)       v = Wq[(size_t)k * (NH*DH) + n];
        else if (n < 1280)  v = Wk[(size_t)k * (NKV*DH) + (n - 1024)];
        else                v = Wv[(size_t)k * (NKV*DH) + (n - 1280)];
        g_wqkvT[(size_t)n * DM + k] = __float2half(v);
    } else {
        int j = idx - QKV_TOT;
        if (j >= DM * DM) return;
        int n = j >> 10, k = j & 1023;
        g_woT[(size_t)n * DM + k] = __float2half(Wo[(size_t)k * DM + n]);
    }
}

// ---------------------------------------------------------------------------
// HMMA helpers (fp16)
// ---------------------------------------------------------------------------
__device__ __forceinline__ uint32_t smem_u32(const void* p) {
    uint32_t a;
    asm("{ .reg .u64 t; cvta.to.shared.u64 t, %1; cvt.u32.u64 %0, t; }" : "=r"(a) : "l"(p));
    return a;
}
__device__ __forceinline__ void ldsm4(uint32_t* r, uint32_t addr) {
    asm volatile("ldmatrix.sync.aligned.m8n8.x4.shared.b16 {%0,%1,%2,%3}, [%4];"
                 : "=r"(r[0]), "=r"(r[1]), "=r"(r[2]), "=r"(r[3]) : "r"(addr));
}
__device__ __forceinline__ void ldsm4t(uint32_t* r, uint32_t addr) {
    asm volatile("ldmatrix.sync.aligned.m8n8.x4.trans.shared.b16 {%0,%1,%2,%3}, [%4];"
                 : "=r"(r[0]), "=r"(r[1]), "=r"(r[2]), "=r"(r[3]) : "r"(addr));
}
__device__ __forceinline__ void mma16816h(float* d, const uint32_t* a, uint32_t b0, uint32_t b1) {
    asm volatile("mma.sync.aligned.m16n8k16.row.col.f32.f16.f16.f32 "
                 "{%0,%1,%2,%3}, {%4,%5,%6,%7}, {%8,%9}, {%0,%1,%2,%3};"
                 : "+f"(d[0]), "+f"(d[1]), "+f"(d[2]), "+f"(d[3])
                 : "r"(a[0]), "r"(a[1]), "r"(a[2]), "r"(a[3]), "r"(b0), "r"(b1));
}
__device__ __forceinline__ void cp16(uint32_t dst, const void* src) {
    asm volatile("cp.async.cg.shared.global [%0], [%1], 16;" :: "r"(dst), "l"(src) : "memory");
}
__device__ __forceinline__ void cp_commit() {
    asm volatile("cp.async.commit_group;" ::: "memory");
}
template <int N>
__device__ __forceinline__ void cp_wait() {
    asm volatile("cp.async.wait_group %0;" :: "n"(N) : "memory");
}
__device__ __forceinline__ uint32_t pkh(float a, float b) {
    __half2 t = __floats2half2_rn(a, b);
    return *(uint32_t*)&t;
}

// ---------------------------------------------------------------------------
// HMMA fp16 GEMM: C[M,N] = A[M,Kt] @ B[N,Kt]^T
// CTA 128x256, 8 warps (2m x 4n of 64x64 warp tiles), BK=32, 3-stage cp.async.
// qkv_mode: N-cols >=1280 are V -> write single fp16 to g_vh instead of fp32 C.
// ---------------------------------------------------------------------------
#define BK     32
#define ROWB   80
#define ATILE  (128 * ROWB)
#define BTILE  (256 * ROWB)
#define STAGE  (ATILE + BTILE)
#define GSMEM  (3 * STAGE)               // 92160

__global__ void __launch_bounds__(256) hmma_gemm2_kernel(
    const __half* __restrict__ A, const __half* __restrict__ B,
    float* __restrict__ C, int Kt, int ldc, int qkv_mode)
{
    extern __shared__ __align__(16) char dsm[];
    const int tid = threadIdx.x;
    const int wid = tid >> 5;
    const int lid = tid & 31;
    const int m0 = blockIdx.x * 128;
    const int n0 = blockIdx.y * 256;
    const int wm = (wid & 1) * 64;
    const int wn = (wid >> 1) * 64;

    uint32_t sA[3], sB[3];
    #pragma unroll
    for (int s = 0; s < 3; s++) {
        sA[s] = smem_u32(dsm + s * STAGE);
        sB[s] = sA[s] + ATILE;
    }

    float acc[4][8][4];
    #pragma unroll
    for (int i = 0; i < 4; i++)
        #pragma unroll
        for (int j = 0; j < 8; j++)
            #pragma unroll
            for (int q = 0; q < 4; q++) acc[i][j][q] = 0.f;

    const int ar = tid >> 2;
    const int ac = (tid & 3) * 16;
    const int NC = Kt / BK;

    #pragma unroll
    for (int c = 0; c < 2; c++) {
        const int k0e = c * BK + (ac >> 1);
        #pragma unroll
        for (int i = 0; i < 2; i++)
            cp16(sA[c] + (ar + i * 64) * ROWB + ac, A + (size_t)(m0 + ar + i * 64) * Kt + k0e);
        #pragma unroll
        for (int i = 0; i < 4; i++)
            cp16(sB[c] + (ar + i * 64) * ROWB + ac, B + (size_t)(n0 + ar + i * 64) * Kt + k0e);
        cp_commit();
    }

    int buf = 0, nbuf = 2;
    for (int c = 0; c < NC; c++) {
        cp_wait<1>();
        __syncthreads();

        if (c + 2 < NC) {
            const int k0e = (c + 2) * BK + (ac >> 1);
            #pragma unroll
            for (int i = 0; i < 2; i++)
                cp16(sA[nbuf] + (ar + i * 64) * ROWB + ac, A + (size_t)(m0 + ar + i * 64) * Kt + k0e);
            #pragma unroll
            for (int i = 0; i < 4; i++)
                cp16(sB[nbuf] + (ar + i * 64) * ROWB + ac, B + (size_t)(n0 + ar + i * 64) * Kt + k0e);
        }
        cp_commit();

        const int lr = lid & 15;
        const int lh = (lid >> 4) * 16;
        #pragma unroll
        for (int ks = 0; ks < 2; ks++) {
            const int kb = ks * 32;
            uint32_t am[4][4], bm[4][4];
            #pragma unroll
            for (int mf = 0; mf < 4; mf++)
                ldsm4(am[mf], sA[buf] + (wm + mf * 16 + lr) * ROWB + kb + lh);
            #pragma unroll
            for (int ng = 0; ng < 4; ng++)
                ldsm4(bm[ng], sB[buf] + (wn + ng * 16 + lr) * ROWB + kb + lh);
            #pragma unroll
            for (int mf = 0; mf < 4; mf++)
                #pragma unroll
                for (int nf = 0; nf < 8; nf++)
                    mma16816h(acc[mf][nf], am[mf], bm[nf >> 1][nf & 1], bm[nf >> 1][(nf & 1) + 2]);
        }
        buf = (buf == 2) ? 0 : buf + 1;
        nbuf = (nbuf == 2) ? 0 : nbuf + 1;
    }

    const int qr = lid >> 2;
    const int qc = (lid & 3) * 2;
    #pragma unroll
    for (int mf = 0; mf < 4; mf++) {
        const int row0 = m0 + wm + mf * 16 + qr;
        #pragma unroll
        for (int nf = 0; nf < 8; nf++) {
            const int col = n0 + wn + nf * 8 + qc;
            if (qkv_mode && col >= 1280) {
                // V output: single fp16 into g_vh [ROWS, 256]
                __half* v0 = g_vh + (size_t)row0 * (NKV*DH) + (col - 1280);
                *(__half2*)v0            = __floats2half2_rn(acc[mf][nf][0], acc[mf][nf][1]);
                *(__half2*)(v0 + 8*(NKV*DH)) = __floats2half2_rn(acc[mf][nf][2], acc[mf][nf][3]);
            } else {
                float* p0 = C + (size_t)row0 * ldc + col;
                float* p1 = p0 + 8 * ldc;
                p0[0] = acc[mf][nf][0]; p0[1] = acc[mf][nf][1];
                p1[0] = acc[mf][nf][2]; p1[1] = acc[mf][nf][3];
            }
        }
    }
}

// ---------------------------------------------------------------------------
// L2 normalize + RoPE; reads fused fp32 proj, writes fp16 Q/K.
// ---------------------------------------------------------------------------
__global__ void __launch_bounds__(256) normrope_kernel(
    const float* __restrict__ cosp, const float* __restrict__ sinp)
{
    int w    = (blockIdx.x * blockDim.x + threadIdx.x) >> 5;
    int lane = threadIdx.x & 31;
    if (w >= ROWS * (NH + NKV)) return;
    int rg = w / (NH + NKV);
    int hh = w - rg * (NH + NKV);
    int s  = rg & (SS - 1);

    const float* base;
    __half* ob;
    if (hh < NH) {
        base = g_qkvlin + (size_t)rg * NQKV + hh * DH;
        ob   = g_qbf    + (size_t)rg * (NH*DH) + hh * DH;
    } else {
        base = g_qkvlin + (size_t)rg * NQKV + 1024 + (hh - NH) * DH;
        ob   = g_kbf    + (size_t)rg * (NKV*DH) + (hh - NH) * DH;
    }

    float v0 = base[lane];
    float v1 = base[lane + 32];
    float ssq = v0*v0 + v1*v1;
    #pragma unroll
    for (int o = 16; o > 0; o >>= 1) ssq += __shfl_xor_sync(0xffffffffu, ssq, o);
    float inv = 1.0f / (sqrtf(ssq) + 1e-8f);

    float x1 = v0 * inv, x2 = v1 * inv;
    float c  = cosp[s*32 + lane];
    float sn = sinp[s*32 + lane];
    ob[lane]      = __float2half(x1*c - x2*sn);
    ob[lane + 32] = __float2half(x1*sn + x2*c);
}

// ---------------------------------------------------------------------------
// HMMA flash attention (fp16): QK single, P single fp16, V single fp16 (1 PV product).
// Writes ctx as single fp16.
// ---------------------------------------------------------------------------
#define ASTR 144

__global__ void __launch_bounds__(128) attn_hmma_kernel()
{
    __shared__ __align__(16) char sQ[64*ASTR];
    __shared__ __align__(16) char sK[64*ASTR];
    __shared__ __align__(16) char sV[64*ASTR];

    const int qt = blockIdx.x, h = blockIdx.y, b = blockIdx.z;
    const int kh = h >> 2;
    const int tid = threadIdx.x;
    const int w = tid >> 5, l = tid & 31;
    const int qs = qt * 64;

    const uint32_t uQ = smem_u32(sQ), uK = smem_u32(sK), uV = smem_u32(sV);

    {
        const char* qb = (const char*)(g_qbf + (size_t)(b*SS + qs) * (NH*DH) + h * DH);
        #pragma unroll
        for (int i = 0; i < 4; i++) {
            int id = tid + i * 128;
            int r = id >> 3, c = (id & 7) * 16;
            cp16(uQ + r * ASTR + c, qb + (size_t)r * (NH*DH*2) + c);
        }
        cp_commit();
    }

    float acc[8][4];
    #pragma unroll
    for (int j = 0; j < 8; j++)
        #pragma unroll
        for (int e = 0; e < 4; e++) acc[j][e] = 0.f;
    float lsum0 = 0.f, lsum1 = 0.f;

    const int kt0 = (qs >= WINDOW) ? ((qs - (WINDOW-1)) >> 6) : 0;
    const int nsteps = qt - kt0 + 1 + (kt0 > 0 ? 1 : 0);

    for (int step = 0; step < nsteps; step++) {
        const int kt = (kt0 > 0) ? (step == 0 ? 0 : kt0 + step - 1) : step;

        __syncthreads();
        {
            const size_t roff = (size_t)(b*SS + kt*64) * (NKV*DH) + kh * DH;
            const char* kb = (const char*)(g_kbf + roff);
            const char* vb = (const char*)(g_vh  + roff);
            #pragma unroll
            for (int i = 0; i < 4; i++) {
                int id = tid + i * 128;
                int r = id >> 3, c = (id & 7) * 16;
                cp16(uK + r * ASTR + c, kb + (size_t)r * (NKV*DH*2) + c);
                cp16(uV + r * ASTR + c, vb + (size_t)r * (NKV*DH*2) + c);
            }
        }
        cp_commit();
        cp_wait<0>();
        __syncthreads();

        float sc[8][4];
        #pragma unroll
        for (int j = 0; j < 8; j++)
            #pragma unroll
            for (int e = 0; e < 4; e++) sc[j][e] = 0.f;

        #pragma unroll
        for (int kf = 0; kf < 4; kf++) {
            uint32_t am[4];
            ldsm4(am, uQ + ((w << 4) + (l & 15)) * ASTR + kf * 32 + ((l >> 4) << 4));
            #pragma unroll
            for (int ng = 0; ng < 4; ng++) {
                uint32_t bm[4];
                ldsm4(bm, uK + (16*ng + (l & 7) + ((l >> 4) << 3)) * ASTR
                             + kf * 32 + (((l >> 3) & 1) << 4));
                mma16816h(sc[2*ng],     am, bm[0], bm[1]);
                mma16816h(sc[2*ng + 1], am, bm[2], bm[3]);
            }
        }

        const int qa0 = qs + (w << 4) + (l >> 2);
        const int kbb = kt * 64 + 2 * (l & 3);
        #pragma unroll
        for (int j = 0; j < 8; j++) {
            const int kc = kbb + 8 * j;
            #pragma unroll
            for (int e = 0; e < 4; e++) {
                const int q_ = qa0 + ((e >> 1) << 3);
                const int k_ = kc + (e & 1);
                const bool v_ = (k_ <= q_) && ((k_ > q_ - WINDOW) || (k_ < NGLOB));
                float p = v_ ? __expf(0.125f * sc[j][e]) : 0.f;
                sc[j][e] = p;
                if (e < 2) lsum0 += p; else lsum1 += p;
            }
        }

        // PV: single product, P rounded to fp16 in registers
        #pragma unroll
        for (int kf = 0; kf < 4; kf++) {
            uint32_t ah[4];
            ah[0] = pkh(sc[2*kf][0],     sc[2*kf][1]);
            ah[1] = pkh(sc[2*kf][2],     sc[2*kf][3]);
            ah[2] = pkh(sc[2*kf + 1][0], sc[2*kf + 1][1]);
            ah[3] = pkh(sc[2*kf + 1][2], sc[2*kf + 1][3]);

            const uint32_t voff = (16*kf + (l & 7) + (((l >> 3) & 1) << 3)) * ASTR
                                  + ((l >> 4) << 4);
            #pragma unroll
            for (int dg = 0; dg < 4; dg++) {
                uint32_t bh[4];
                ldsm4t(bh, uV + voff + dg * 32);
                mma16816h(acc[2*dg],     ah, bh[0], bh[1]);
                mma16816h(acc[2*dg + 1], ah, bh[2], bh[3]);
            }
        }
    }

    // epilogue: normalize + write ctx single fp16
    lsum0 += __shfl_xor_sync(0xffffffffu, lsum0, 1, 4);
    lsum0 += __shfl_xor_sync(0xffffffffu, lsum0, 2, 4);
    lsum1 += __shfl_xor_sync(0xffffffffu, lsum1, 1, 4);
    lsum1 += __shfl_xor_sync(0xffffffffu, lsum1, 2, 4);
    const float i0 = 1.f / lsum0;
    const float i1 = 1.f / lsum1;

    const size_t row0 = (size_t)(b*SS + qs + (w << 4) + (l >> 2));
    __half* cb0 = g_ctxh + row0 * DM + h * DH + 2 * (l & 3);
    __half* cb1 = cb0 + 8 * DM;
    #pragma unroll
    for (int j = 0; j < 8; j++) {
        *(__half2*)(cb0 + 8*j) = __floats2half2_rn(acc[j][0] * i0, acc[j][1] * i0);
        *(__half2*)(cb1 + 8*j) = __floats2half2_rn(acc[j][2] * i1, acc[j][3] * i1);
    }
}

// ---------------------------------------------------------------------------
// Launch
// ---------------------------------------------------------------------------
extern "C" void kernel_launch(void* const* d_in, const int* in_sizes, int n_in,
                              void* d_out, int out_size)
{
    const float* x    = (const float*)d_in[0];
    const float* cosp = (const float*)d_in[1];
    const float* sinp = (const float*)d_in[2];
    // d_in[3] = mask: deterministic causal -> computed analytically in-kernel
    const float* Wq   = (const float*)d_in[4];
    const float* Wk   = (const float*)d_in[5];
    const float* Wv   = (const float*)d_in[6];
    const float* Wo   = (const float*)d_in[7];
    float* out = (float*)d_out;

    void *p_qkv, *p_xh, *p_ch, *p_wqkvT, *p_woT;
    cudaGetSymbolAddress(&p_qkv,   g_qkvlin);
    cudaGetSymbolAddress(&p_xh,    g_xh);
    cudaGetSymbolAddress(&p_ch,    g_ctxh);
    cudaGetSymbolAddress(&p_wqkvT, g_wqkvT);
    cudaGetSymbolAddress(&p_woT,   g_woT);

    cudaFuncSetAttribute(hmma_gemm2_kernel, cudaFuncAttributeMaxDynamicSharedMemorySize, GSMEM);

    // 0) Conversions
    conv_x_kernel<<<(ROWS*DM + 255)/256, 256>>>(x);
    conv_weights_kernel<<<((NQKV*DM + DM*DM) + 255)/256, 256>>>(Wq, Wk, Wv, Wo);

    // 1) Fused QKV projection (V cols emitted as fp16 directly)
    hmma_gemm2_kernel<<<dim3(ROWS/128, NQKV/256), 256, GSMEM>>>(
        (const __half*)p_xh, (const __half*)p_wqkvT, (float*)p_qkv, DM, NQKV, 1);

    // 2) L2 norm + RoPE -> fp16 Q/K
    {
        int warps = ROWS * (NH + NKV);
        int blocks = (warps * 32 + 255) / 256;
        normrope_kernel<<<blocks, 256>>>(cosp, sinp);
    }

    // 3) Attention (fp16 HMMA, 1 PV product, writes fp16 ctx)
    attn_hmma_kernel<<<dim3(SS/64, NH, BB), 128>>>();

    // 4) Output projection (K=1024)
    hmma_gemm2_kernel<<<dim3(ROWS/128, DM/256), 256, GSMEM>>>(
        (const __half*)p_ch, (const __half*)p_woT, out, DM, DM, 0);
}